// round 7
// baseline (speedup 1.0000x reference)
#include <cuda_runtime.h>
#include <cuda_bf16.h>
#include <cstdint>

// Problem constants
#define QLEN 1024
#define MLEN 1024
#define KLEN 2048   // QLEN + MLEN
#define BSZ  4
#define NH   8
#define DH   64
#define DM   512    // NH*DH
#define SCALE 0.125f
#define LN_EPS 1e-5f

// ---------------------------------------------------------------------------
// Scratch (device globals; allocation inside kernel_launch is forbidden)
// ---------------------------------------------------------------------------
__device__ float g_kv [ (size_t)KLEN * BSZ * 2 * DM ];  // [klen*bsz, 1024] (k | v)
__device__ float g_q  [ (size_t)QLEN * BSZ * DM ];      // [qlen*bsz, 512]
__device__ float g_rk [ (size_t)KLEN * DM ];            // [klen, 512]
__device__ float g_vec[ (size_t)QLEN * BSZ * DM ];      // attn_vec
__device__ float g_ao [ (size_t)QLEN * BSZ * DM ];      // attn_out

// ---------------------------------------------------------------------------
// SGEMM: C[M,N] = A[M,K] @ B[K,N], row-major, fp32.
// BM=128, BN=64, BK=16, 256 threads, 8x4 per-thread microtile.
// Requires M%128==0, N%64==0, K%16==0 (true for all uses here).
// ---------------------------------------------------------------------------
#define BM 128
#define BN 64
#define BKK 16

__global__ __launch_bounds__(256) void sgemm_k(
    const float* __restrict__ A, const float* __restrict__ B,
    float* __restrict__ C, int M, int N, int K)
{
    __shared__ float As[BKK][BM + 4];
    __shared__ float Bs[BKK][BN + 4];

    const int tid = threadIdx.x;
    const int tx = tid & 15;
    const int ty = tid >> 4;
    const int m0 = blockIdx.y * BM;
    const int n0 = blockIdx.x * BN;

    const int arow = tid >> 2;        // 0..63
    const int akg  = (tid & 3) * 4;   // 0,4,8,12
    const int brow = tid >> 4;        // 0..15
    const int bcol = (tid & 15) * 4;

    float acc[8][4];
#pragma unroll
    for (int i = 0; i < 8; i++)
#pragma unroll
        for (int j = 0; j < 4; j++) acc[i][j] = 0.f;

    for (int k0 = 0; k0 < K; k0 += BKK) {
        // load A tile (transposed into As[k][m])
#pragma unroll
        for (int r = 0; r < 2; r++) {
            int m = arow + r * 64;
            float4 v = *(const float4*)(A + (size_t)(m0 + m) * K + k0 + akg);
            As[akg + 0][m] = v.x;
            As[akg + 1][m] = v.y;
            As[akg + 2][m] = v.z;
            As[akg + 3][m] = v.w;
        }
        // load B tile
        {
            float4 v = *(const float4*)(B + (size_t)(k0 + brow) * N + n0 + bcol);
            *(float4*)&Bs[brow][bcol] = v;
        }
        __syncthreads();

#pragma unroll
        for (int k = 0; k < BKK; k++) {
            float4 a0 = *(float4*)&As[k][ty * 8];
            float4 a1 = *(float4*)&As[k][ty * 8 + 4];
            float4 bb = *(float4*)&Bs[k][tx * 4];
            float av[8] = {a0.x, a0.y, a0.z, a0.w, a1.x, a1.y, a1.z, a1.w};
            float bv[4] = {bb.x, bb.y, bb.z, bb.w};
#pragma unroll
            for (int i = 0; i < 8; i++)
#pragma unroll
                for (int j = 0; j < 4; j++)
                    acc[i][j] += av[i] * bv[j];
        }
        __syncthreads();
    }

#pragma unroll
    for (int i = 0; i < 8; i++) {
        float4 v = make_float4(acc[i][0], acc[i][1], acc[i][2], acc[i][3]);
        *(float4*)(C + (size_t)(m0 + ty * 8 + i) * N + n0 + tx * 4) = v;
    }
}

// ---------------------------------------------------------------------------
// Fused flash attention with Transformer-XL relative bias.
//   score[i,j] = ( (q_i + rwb) . k_j  +  (q_i + rrb) . rk[j - i + QLEN-1] ) * SCALE
//   masked where j > i + MLEN; online softmax; accumulate P@V.
// Grid: (QLEN/64, BSZ*NH). Block: 256 threads (16x16), 4x4 microtile.
// Dynamic smem: 103680 bytes.
// ---------------------------------------------------------------------------
#define ATTN_SMEM_FLOATS (4*64*68 + 64*132 + 64)
#define ATTN_SMEM_BYTES  (ATTN_SMEM_FLOATS * 4)

__global__ __launch_bounds__(256) void attn_kernel(
    const float* __restrict__ qb,    // [qlen*bsz, 512]
    const float* __restrict__ kvb,   // [klen*bsz, 1024]
    const float* __restrict__ rkb,   // [klen, 512]
    const float* __restrict__ rwb,   // [8,64]
    const float* __restrict__ rrb,   // [8,64]
    float* __restrict__ vec)         // [qlen*bsz, 512]
{
    extern __shared__ float sh[];
    float* sh_q    = sh;                    // [k][i]  64 x 68  (q + rwb, transposed)
    float* sh_k    = sh_q  + 64 * 68;       // [k][j]  64 x 68
    float* sh_rk   = sh_k  + 64 * 68;       // [k][rr] 64 x 132 (128-row window)
    float* sh_v    = sh_rk + 64 * 132;      // [j][d]  64 x 68
    float* sh_p    = sh_v  + 64 * 68;       // [j][i]  64 x 68
    float* sh_diff = sh_p  + 64 * 68;       // [64] = rrb - rwb

    const int tid = threadIdx.x;
    const int tx = tid & 15;
    const int ty = tid >> 4;
    const int bn = blockIdx.y;
    const int b = bn >> 3;
    const int n = bn & 7;
    const int i0 = blockIdx.x * 64;
    const int iw = ty * 4;   // local i base
    const int jc = tx * 4;   // local j base (also out-dim base in PV)

    // Load q tile (+ r_w_bias), transposed to [k][i]
    for (int idx = tid; idx < 64 * 64; idx += 256) {
        int ii = idx >> 6, k = idx & 63;
        float qv = qb[(size_t)((i0 + ii) * BSZ + b) * DM + n * DH + k] + rwb[n * DH + k];
        sh_q[k * 68 + ii] = qv;
    }
    if (tid < 64) sh_diff[tid] = rrb[n * DH + tid] - rwb[n * DH + tid];

    float m[4], l[4], o[4][4];
#pragma unroll
    for (int i = 0; i < 4; i++) {
        m[i] = -1e30f; l[i] = 0.f;
#pragma unroll
        for (int j = 0; j < 4; j++) o[i][j] = 0.f;
    }

    const int ntiles = blockIdx.x + 17;   // last j tile touching i0+63+MLEN
    for (int t = 0; t < ntiles; t++) {
        const int j0 = t * 64;
        __syncthreads();   // protect sh_k/sh_v/sh_rk/sh_p from previous iteration

        // Load K (transposed [k][j]) and V ([j][d])
        for (int idx = tid; idx < 64 * 64; idx += 256) {
            int jj = idx >> 6, k = idx & 63;
            size_t base = (size_t)((j0 + jj) * BSZ + b) * (2 * DM) + n * DH + k;
            sh_k[k * 68 + jj] = kvb[base];
            sh_v[jj * 68 + k] = kvb[base + DM];
        }
        // Load rk window: rows dbase .. dbase+127, transposed [k][rr]
        const int dbase = j0 - i0 + (QLEN - 64);  // j0 - i0 + 960
        for (int idx = tid; idx < 128 * 64; idx += 256) {
            int rr = idx >> 6, k = idx & 63;
            int d = dbase + rr;
            float v = 0.f;
            if (d >= 0 && d < KLEN) v = rkb[(size_t)d * DM + n * DH + k];
            sh_rk[k * 132 + rr] = v;
        }
        __syncthreads();

        // ---- scores: AC + skewed BD ----
        float ac[4][4], bd[4][4];
#pragma unroll
        for (int i = 0; i < 4; i++)
#pragma unroll
            for (int j = 0; j < 4; j++) { ac[i][j] = 0.f; bd[i][j] = 0.f; }

        const int rel0 = jc - iw + 60;   // in [0,120]; thread needs rel0..rel0+6
#pragma unroll 4
        for (int k = 0; k < 64; k++) {
            float4 a4 = *(float4*)(sh_q  + k * 68  + iw);
            float4 b4 = *(float4*)(sh_k  + k * 68  + jc);
            float4 r0 = *(float4*)(sh_rk + k * 132 + rel0);
            float4 r1 = *(float4*)(sh_rk + k * 132 + rel0 + 4);
            float dk = sh_diff[k];
            float av[4] = {a4.x, a4.y, a4.z, a4.w};
            float bv[4] = {b4.x, b4.y, b4.z, b4.w};
            float rv[8] = {r0.x, r0.y, r0.z, r0.w, r1.x, r1.y, r1.z, r1.w};
#pragma unroll
            for (int ii = 0; ii < 4; ii++) {
                float ar = av[ii] + dk;
#pragma unroll
                for (int jj = 0; jj < 4; jj++) {
                    ac[ii][jj] += av[ii] * bv[jj];
                    bd[ii][jj] += ar * rv[jj - ii + 3];  // rel = (jc+jj)+63-(iw+ii)
                }
            }
        }

        // ---- mask, online softmax, write P^T ----
#pragma unroll
        for (int ii = 0; ii < 4; ii++) {
            const int ig = i0 + iw + ii;
            float s[4];
            float mx = -1e30f;
#pragma unroll
            for (int jj = 0; jj < 4; jj++) {
                int jg = j0 + jc + jj;
                float v = (ac[ii][jj] + bd[ii][jj]) * SCALE;
                if (jg > ig + MLEN) v = -1e30f;
                s[jj] = v;
                mx = fmaxf(mx, v);
            }
#pragma unroll
            for (int off = 8; off >= 1; off >>= 1)
                mx = fmaxf(mx, __shfl_xor_sync(0xffffffffu, mx, off));
            float mnew = fmaxf(m[ii], mx);
            float f = __expf(m[ii] - mnew);
            float rs = 0.f;
#pragma unroll
            for (int jj = 0; jj < 4; jj++) {
                float p = __expf(s[jj] - mnew);
                sh_p[(jc + jj) * 68 + iw + ii] = p;
                rs += p;
            }
#pragma unroll
            for (int off = 8; off >= 1; off >>= 1)
                rs += __shfl_xor_sync(0xffffffffu, rs, off);
            l[ii] = l[ii] * f + rs;
            m[ii] = mnew;
#pragma unroll
            for (int kk = 0; kk < 4; kk++) o[ii][kk] *= f;
        }
        __syncthreads();

        // ---- P @ V ----
#pragma unroll 4
        for (int j = 0; j < 64; j++) {
            float4 pa = *(float4*)(sh_p + j * 68 + iw);
            float4 vb = *(float4*)(sh_v + j * 68 + jc);
            float pv[4] = {pa.x, pa.y, pa.z, pa.w};
            float vv[4] = {vb.x, vb.y, vb.z, vb.w};
#pragma unroll
            for (int ii = 0; ii < 4; ii++)
#pragma unroll
                for (int kk = 0; kk < 4; kk++)
                    o[ii][kk] += pv[ii] * vv[kk];
        }
    }

    // ---- epilogue: normalize and write attn_vec ----
#pragma unroll
    for (int ii = 0; ii < 4; ii++) {
        float inv = 1.f / l[ii];
        float4 v = make_float4(o[ii][0] * inv, o[ii][1] * inv,
                               o[ii][2] * inv, o[ii][3] * inv);
        *(float4*)(vec + (size_t)((i0 + iw + ii) * BSZ + b) * DM + n * DH + jc) = v;
    }
}

// ---------------------------------------------------------------------------
// Residual + LayerNorm: out[row] = LN(w[row] + attn_out[row]) * g + b
// One CTA (256 threads) per row of 512.
// ---------------------------------------------------------------------------
__global__ __launch_bounds__(256) void ln_kernel(
    const float* __restrict__ w, const float* __restrict__ ao,
    const float* __restrict__ g, const float* __restrict__ bb,
    float* __restrict__ out)
{
    const int row = blockIdx.x;
    const int tid = threadIdx.x;
    const size_t base = (size_t)row * DM;

    float x0 = w[base + tid]       + ao[base + tid];
    float x1 = w[base + tid + 256] + ao[base + tid + 256];
    float s  = x0 + x1;
    float ss = x0 * x0 + x1 * x1;

#pragma unroll
    for (int off = 16; off >= 1; off >>= 1) {
        s  += __shfl_xor_sync(0xffffffffu, s,  off);
        ss += __shfl_xor_sync(0xffffffffu, ss, off);
    }
    __shared__ float sh_s[8], sh_ss[8];
    int wid = tid >> 5, lane = tid & 31;
    if (lane == 0) { sh_s[wid] = s; sh_ss[wid] = ss; }
    __syncthreads();
    if (tid == 0) {
        float a = 0.f, c = 0.f;
#pragma unroll
        for (int i = 0; i < 8; i++) { a += sh_s[i]; c += sh_ss[i]; }
        sh_s[0] = a; sh_ss[0] = c;
    }
    __syncthreads();

    float mean = sh_s[0] * (1.f / (float)DM);
    float var  = sh_ss[0] * (1.f / (float)DM) - mean * mean;
    float rstd = rsqrtf(var + LN_EPS);

    out[base + tid]       = (x0 - mean) * rstd * g[tid]       + bb[tid];
    out[base + tid + 256] = (x1 - mean) * rstd * g[tid + 256] + bb[tid + 256];
}

// ---------------------------------------------------------------------------
// Launcher
// ---------------------------------------------------------------------------
extern "C" void kernel_launch(void* const* d_in, const int* in_sizes, int n_in,
                              void* d_out, int out_size)
{
    const float* w    = (const float*)d_in[0];   // [1024,4,512]
    const float* r    = (const float*)d_in[1];   // [2048,1,512]
    const float* rwb  = (const float*)d_in[2];   // [8,64]
    const float* rrb  = (const float*)d_in[3];   // [8,64]
    const float* mems = (const float*)d_in[4];   // [1024,4,512]
    const float* Wq   = (const float*)d_in[5];   // [512,512]
    const float* Wkv  = (const float*)d_in[6];   // [512,1024]
    const float* Wr   = (const float*)d_in[7];   // [512,512]
    const float* Wo   = (const float*)d_in[8];   // [512,512]
    const float* lng  = (const float*)d_in[9];   // [512]
    const float* lnb  = (const float*)d_in[10];  // [512]
    // d_in[11] = attn_mask: computed analytically, unused.
    float* out = (float*)d_out;

    float *kv, *q, *rk, *vec, *ao;
    cudaGetSymbolAddress((void**)&kv,  g_kv);
    cudaGetSymbolAddress((void**)&q,   g_q);
    cudaGetSymbolAddress((void**)&rk,  g_rk);
    cudaGetSymbolAddress((void**)&vec, g_vec);
    cudaGetSymbolAddress((void**)&ao,  g_ao);

    // kv = cat(mems, w) @ Wkv  — cat flat rows = mems rows then w rows
    sgemm_k<<<dim3(1024 / BN, 4096 / BM), 256>>>(mems, Wkv, kv, 4096, 1024, 512);
    sgemm_k<<<dim3(1024 / BN, 4096 / BM), 256>>>(w, Wkv, kv + (size_t)4096 * 1024, 4096, 1024, 512);
    // q = w @ Wq
    sgemm_k<<<dim3(512 / BN, 4096 / BM), 256>>>(w, Wq, q, 4096, 512, 512);
    // rk = r @ Wr
    sgemm_k<<<dim3(512 / BN, 2048 / BM), 256>>>(r, Wr, rk, 2048, 512, 512);

    // fused attention
    cudaFuncSetAttribute(attn_kernel, cudaFuncAttributeMaxDynamicSharedMemorySize,
                         ATTN_SMEM_BYTES);
    attn_kernel<<<dim3(QLEN / 64, BSZ * NH), 256, ATTN_SMEM_BYTES>>>(q, kv, rk, rwb, rrb, vec);

    // attn_out = vec @ Wo
    sgemm_k<<<dim3(512 / BN, 4096 / BM), 256>>>(vec, Wo, ao, 4096, 512, 512);

    // residual + layernorm -> d_out
    ln_kernel<<<QLEN * BSZ, 256>>>(w, ao, lng, lnb, out);
}

// round 9
// speedup vs baseline: 1.1158x; 1.1158x over previous
#include <cuda_runtime.h>
#include <cuda_bf16.h>
#include <mma.h>
#include <cstdint>

using namespace nvcuda;

// Problem constants
#define QLEN 1024
#define MLEN 1024
#define KLEN 2048   // QLEN + MLEN
#define BSZ  4
#define NH   8
#define DH   64
#define DM   512    // NH*DH
#define SCALE 0.125f
#define LN_EPS 1e-5f
#define KE   1536   // extended K (hi | lo | hi)

// ---------------------------------------------------------------------------
// Scratch (device globals; allocation inside kernel_launch is forbidden)
// ---------------------------------------------------------------------------
__device__ float g_kv [ (size_t)KLEN * BSZ * 2 * DM ];  // [klen*bsz, 1024] (k | v)
__device__ float g_q  [ (size_t)QLEN * BSZ * DM ];
__device__ float g_rk [ (size_t)KLEN * DM ];
__device__ float g_vec[ (size_t)QLEN * BSZ * DM ];
__device__ float g_ao [ (size_t)QLEN * BSZ * DM ];

// Extended bf16 operands (K' = 1536): A rows = [hi | lo | hi]
__device__ __nv_bfloat16 g_ax_mem[(size_t)4096 * KE];
__device__ __nv_bfloat16 g_ax_w  [(size_t)4096 * KE];
__device__ __nv_bfloat16 g_ax_r  [(size_t)2048 * KE];
__device__ __nv_bfloat16 g_ax_v  [(size_t)4096 * KE];
// Transposed extended weights: Bt rows = [hi | hi | lo]
__device__ __nv_bfloat16 g_bt_kv [(size_t)1024 * KE];
__device__ __nv_bfloat16 g_bt_q  [(size_t)512 * KE];
__device__ __nv_bfloat16 g_bt_r  [(size_t)512 * KE];
__device__ __nv_bfloat16 g_bt_o  [(size_t)512 * KE];

// ---------------------------------------------------------------------------
// Small helpers
// ---------------------------------------------------------------------------
__device__ __forceinline__ uint32_t pack_bf2(float a, float b) {
    __nv_bfloat162 t;
    t.x = __float2bfloat16_rn(a);
    t.y = __float2bfloat16_rn(b);
    return *reinterpret_cast<uint32_t*>(&t);
}
__device__ __forceinline__ void cp16(uint32_t dst, const void* src) {
    asm volatile("cp.async.cg.shared.global [%0], [%1], 16;" :: "r"(dst), "l"(src));
}
__device__ __forceinline__ void cp_commit() {
    asm volatile("cp.async.commit_group;" ::: "memory");
}
template<int N> __device__ __forceinline__ void cp_wait() {
    asm volatile("cp.async.wait_group %0;" :: "n"(N) : "memory");
}

// ---------------------------------------------------------------------------
// A-side conversion: A fp32 [M][512] -> Aext bf16 [M][1536] = [hi | lo | hi]
// grid = M/2, block = 256 (each thread: 4 floats)
// ---------------------------------------------------------------------------
__global__ __launch_bounds__(256) void conv_a_ext(
    const float* __restrict__ A, __nv_bfloat16* __restrict__ out)
{
    int idx = blockIdx.x * 256 + threadIdx.x;
    int m = idx >> 7;
    int kg = (idx & 127) * 4;
    float4 v = *(const float4*)(A + (size_t)m * 512 + kg);
    __nv_bfloat16 h0 = __float2bfloat16_rn(v.x), h1 = __float2bfloat16_rn(v.y);
    __nv_bfloat16 h2 = __float2bfloat16_rn(v.z), h3 = __float2bfloat16_rn(v.w);
    uint2 HH, LL;
    { __nv_bfloat162 t; t.x = h0; t.y = h1; HH.x = *(uint32_t*)&t; }
    { __nv_bfloat162 t; t.x = h2; t.y = h3; HH.y = *(uint32_t*)&t; }
    LL.x = pack_bf2(v.x - __bfloat162float(h0), v.y - __bfloat162float(h1));
    LL.y = pack_bf2(v.z - __bfloat162float(h2), v.w - __bfloat162float(h3));
    __nv_bfloat16* row = out + (size_t)m * KE;
    *(uint2*)(row + kg)        = HH;
    *(uint2*)(row + 512 + kg)  = LL;
    *(uint2*)(row + 1024 + kg) = HH;
}

// ---------------------------------------------------------------------------
// Weight transpose + extend: W fp32 [512][N] -> Bt bf16 [N][1536] = [hi|hi|lo]
// block (32,8), grid (N/32, 512/32)
// ---------------------------------------------------------------------------
__global__ __launch_bounds__(256) void conv_bt_ext(
    const float* __restrict__ W, __nv_bfloat16* __restrict__ bt, int N)
{
    __shared__ float t[32][33];
    const int n0 = blockIdx.x * 32, k0 = blockIdx.y * 32;
    const int tx = threadIdx.x, ty = threadIdx.y;
#pragma unroll
    for (int r = 0; r < 32; r += 8)
        t[ty + r][tx] = W[(size_t)(k0 + ty + r) * N + n0 + tx];
    __syncthreads();
#pragma unroll
    for (int r = 0; r < 32; r += 8) {
        float x = t[tx][ty + r];
        __nv_bfloat16 h = __float2bfloat16_rn(x);
        __nv_bfloat16 l = __float2bfloat16_rn(x - __bfloat162float(h));
        __nv_bfloat16* row = bt + (size_t)(n0 + ty + r) * KE;
        row[k0 + tx]        = h;
        row[512 + k0 + tx]  = h;
        row[1024 + k0 + tx] = l;
    }
}

// ---------------------------------------------------------------------------
// bf16 WMMA GEMM: C[M,N] fp32 = Aext[M,KE] @ Bt[N,KE]^T
// CTA tile 128x128, 8 warps (warp tile 32x64 = 2x4 wmma m16n16k16),
// K-stage 32, cp.async double-buffered.
// ---------------------------------------------------------------------------
#define LDT 40   // padded smem row (bf16 elems); 80B stride, conflict-friendly

__global__ __launch_bounds__(256) void hgemm(
    const __nv_bfloat16* __restrict__ A,   // [M][KE]
    const __nv_bfloat16* __restrict__ Bt,  // [N][KE]
    float* __restrict__ C, int M, int N)
{
    __shared__ __nv_bfloat16 As[2][128 * LDT];
    __shared__ __nv_bfloat16 Bs[2][128 * LDT];

    const int tid = threadIdx.x;
    const int wid = tid >> 5;
    const int m0 = blockIdx.y * 128, n0 = blockIdx.x * 128;
    const int wm = (wid >> 1) * 32;     // warp m offset (0,32,64,96)
    const int wn = (wid & 1) * 64;      // warp n offset (0,64)

    const uint32_t as0 = (uint32_t)__cvta_generic_to_shared(&As[0][0]);
    const uint32_t as1 = (uint32_t)__cvta_generic_to_shared(&As[1][0]);
    const uint32_t bs0 = (uint32_t)__cvta_generic_to_shared(&Bs[0][0]);
    const uint32_t bs1 = (uint32_t)__cvta_generic_to_shared(&Bs[1][0]);

    wmma::fragment<wmma::accumulator, 16, 16, 16, float> cf[2][4];
#pragma unroll
    for (int i = 0; i < 2; i++)
#pragma unroll
        for (int j = 0; j < 4; j++) wmma::fill_fragment(cf[i][j], 0.f);

    // stage loader: 128 rows x 32 bf16 (64B) each for A and B
    auto load_stage = [&](int s, int kc) {
        uint32_t ab = s ? as1 : as0;
        uint32_t bb = s ? bs1 : bs0;
#pragma unroll
        for (int rep = 0; rep < 2; rep++) {
            int chunk = tid + rep * 256;          // 0..511
            int row = chunk >> 2;
            int c = (chunk & 3) * 8;              // bf16 elems (8 per 16B)
            cp16(ab + (uint32_t)(row * LDT + c) * 2,
                 A + (size_t)(m0 + row) * KE + kc + c);
            cp16(bb + (uint32_t)(row * LDT + c) * 2,
                 Bt + (size_t)(n0 + row) * KE + kc + c);
        }
    };

    load_stage(0, 0);
    cp_commit();

    const int NKC = KE / 32;   // 48
    for (int kc = 0; kc < NKC; kc++) {
        int cur = kc & 1;
        if (kc + 1 < NKC) {
            load_stage(cur ^ 1, (kc + 1) * 32);
            cp_commit();
            cp_wait<1>();
        } else {
            cp_wait<0>();
        }
        __syncthreads();

#pragma unroll
        for (int kk = 0; kk < 32; kk += 16) {
            wmma::fragment<wmma::matrix_a, 16, 16, 16, __nv_bfloat16, wmma::row_major> af[2];
            wmma::fragment<wmma::matrix_b, 16, 16, 16, __nv_bfloat16, wmma::col_major> bf[4];
#pragma unroll
            for (int i = 0; i < 2; i++)
                wmma::load_matrix_sync(af[i], &As[cur][(wm + i * 16) * LDT + kk], LDT);
#pragma unroll
            for (int j = 0; j < 4; j++)
                wmma::load_matrix_sync(bf[j], &Bs[cur][(wn + j * 16) * LDT + kk], LDT);
#pragma unroll
            for (int i = 0; i < 2; i++)
#pragma unroll
                for (int j = 0; j < 4; j++)
                    wmma::mma_sync(cf[i][j], af[i], bf[j], cf[i][j]);
        }
        __syncthreads();
    }

#pragma unroll
    for (int i = 0; i < 2; i++)
#pragma unroll
        for (int j = 0; j < 4; j++)
            wmma::store_matrix_sync(C + (size_t)(m0 + wm + i * 16) * N + n0 + wn + j * 16,
                                    cf[i][j], N, wmma::mem_row_major);
}

// ---------------------------------------------------------------------------
// Fused flash attention with Transformer-XL relative bias (fp32, validated).
// ---------------------------------------------------------------------------
#define ATTN_SMEM_FLOATS (4*64*68 + 64*132 + 64)
#define ATTN_SMEM_BYTES  (ATTN_SMEM_FLOATS * 4)

__global__ __launch_bounds__(256) void attn_kernel(
    const float* __restrict__ qb, const float* __restrict__ kvb,
    const float* __restrict__ rkb, const float* __restrict__ rwb,
    const float* __restrict__ rrb, float* __restrict__ vec)
{
    extern __shared__ float sh[];
    float* sh_q    = sh;
    float* sh_k    = sh_q  + 64 * 68;
    float* sh_rk   = sh_k  + 64 * 68;
    float* sh_v    = sh_rk + 64 * 132;
    float* sh_p    = sh_v  + 64 * 68;
    float* sh_diff = sh_p  + 64 * 68;

    const int tid = threadIdx.x;
    const int tx = tid & 15;
    const int ty = tid >> 4;
    const int bn = blockIdx.y;
    const int b = bn >> 3;
    const int n = bn & 7;
    const int i0 = blockIdx.x * 64;
    const int iw = ty * 4;
    const int jc = tx * 4;

    for (int idx = tid; idx < 64 * 64; idx += 256) {
        int ii = idx >> 6, k = idx & 63;
        float qv = qb[(size_t)((i0 + ii) * BSZ + b) * DM + n * DH + k] + rwb[n * DH + k];
        sh_q[k * 68 + ii] = qv;
    }
    if (tid < 64) sh_diff[tid] = rrb[n * DH + tid] - rwb[n * DH + tid];

    float m[4], l[4], o[4][4];
#pragma unroll
    for (int i = 0; i < 4; i++) {
        m[i] = -1e30f; l[i] = 0.f;
#pragma unroll
        for (int j = 0; j < 4; j++) o[i][j] = 0.f;
    }

    const int ntiles = blockIdx.x + 17;
    for (int t = 0; t < ntiles; t++) {
        const int j0 = t * 64;
        __syncthreads();

        for (int idx = tid; idx < 64 * 64; idx += 256) {
            int jj = idx >> 6, k = idx & 63;
            size_t base = (size_t)((j0 + jj) * BSZ + b) * (2 * DM) + n * DH + k;
            sh_k[k * 68 + jj] = kvb[base];
            sh_v[jj * 68 + k] = kvb[base + DM];
        }
        const int dbase = j0 - i0 + (QLEN - 64);
        for (int idx = tid; idx < 128 * 64; idx += 256) {
            int rr = idx >> 6, k = idx & 63;
            int d = dbase + rr;
            float v = 0.f;
            if (d >= 0 && d < KLEN) v = rkb[(size_t)d * DM + n * DH + k];
            sh_rk[k * 132 + rr] = v;
        }
        __syncthreads();

        float ac[4][4], bd[4][4];
#pragma unroll
        for (int i = 0; i < 4; i++)
#pragma unroll
            for (int j = 0; j < 4; j++) { ac[i][j] = 0.f; bd[i][j] = 0.f; }

        const int rel0 = jc - iw + 60;
#pragma unroll 4
        for (int k = 0; k < 64; k++) {
            float4 a4 = *(float4*)(sh_q  + k * 68  + iw);
            float4 b4 = *(float4*)(sh_k  + k * 68  + jc);
            float4 r0 = *(float4*)(sh_rk + k * 132 + rel0);
            float4 r1 = *(float4*)(sh_rk + k * 132 + rel0 + 4);
            float dk = sh_diff[k];
            float av[4] = {a4.x, a4.y, a4.z, a4.w};
            float bv[4] = {b4.x, b4.y, b4.z, b4.w};
            float rv[8] = {r0.x, r0.y, r0.z, r0.w, r1.x, r1.y, r1.z, r1.w};
#pragma unroll
            for (int ii = 0; ii < 4; ii++) {
                float ar = av[ii] + dk;
#pragma unroll
                for (int jj = 0; jj < 4; jj++) {
                    ac[ii][jj] += av[ii] * bv[jj];
                    bd[ii][jj] += ar * rv[jj - ii + 3];
                }
            }
        }

#pragma unroll
        for (int ii = 0; ii < 4; ii++) {
            const int ig = i0 + iw + ii;
            float s[4];
            float mx = -1e30f;
#pragma unroll
            for (int jj = 0; jj < 4; jj++) {
                int jg = j0 + jc + jj;
                float v = (ac[ii][jj] + bd[ii][jj]) * SCALE;
                if (jg > ig + MLEN) v = -1e30f;
                s[jj] = v;
                mx = fmaxf(mx, v);
            }
#pragma unroll
            for (int off = 8; off >= 1; off >>= 1)
                mx = fmaxf(mx, __shfl_xor_sync(0xffffffffu, mx, off));
            float mnew = fmaxf(m[ii], mx);
            float f = __expf(m[ii] - mnew);
            float rs = 0.f;
#pragma unroll
            for (int jj = 0; jj < 4; jj++) {
                float p = __expf(s[jj] - mnew);
                sh_p[(jc + jj) * 68 + iw + ii] = p;
                rs += p;
            }
#pragma unroll
            for (int off = 8; off >= 1; off >>= 1)
                rs += __shfl_xor_sync(0xffffffffu, rs, off);
            l[ii] = l[ii] * f + rs;
            m[ii] = mnew;
#pragma unroll
            for (int kk = 0; kk < 4; kk++) o[ii][kk] *= f;
        }
        __syncthreads();

#pragma unroll 4
        for (int j = 0; j < 64; j++) {
            float4 pa = *(float4*)(sh_p + j * 68 + iw);
            float4 vb = *(float4*)(sh_v + j * 68 + jc);
            float pv[4] = {pa.x, pa.y, pa.z, pa.w};
            float vv[4] = {vb.x, vb.y, vb.z, vb.w};
#pragma unroll
            for (int ii = 0; ii < 4; ii++)
#pragma unroll
                for (int kk = 0; kk < 4; kk++)
                    o[ii][kk] += pv[ii] * vv[kk];
        }
    }

#pragma unroll
    for (int ii = 0; ii < 4; ii++) {
        float inv = 1.f / l[ii];
        float4 v = make_float4(o[ii][0] * inv, o[ii][1] * inv,
                               o[ii][2] * inv, o[ii][3] * inv);
        *(float4*)(vec + (size_t)((i0 + iw + ii) * BSZ + b) * DM + n * DH + jc) = v;
    }
}

// ---------------------------------------------------------------------------
// Residual + LayerNorm (unchanged)
// ---------------------------------------------------------------------------
__global__ __launch_bounds__(256) void ln_kernel(
    const float* __restrict__ w, const float* __restrict__ ao,
    const float* __restrict__ g, const float* __restrict__ bb,
    float* __restrict__ out)
{
    const int row = blockIdx.x;
    const int tid = threadIdx.x;
    const size_t base = (size_t)row * DM;

    float x0 = w[base + tid]       + ao[base + tid];
    float x1 = w[base + tid + 256] + ao[base + tid + 256];
    float s  = x0 + x1;
    float ss = x0 * x0 + x1 * x1;

#pragma unroll
    for (int off = 16; off >= 1; off >>= 1) {
        s  += __shfl_xor_sync(0xffffffffu, s,  off);
        ss += __shfl_xor_sync(0xffffffffu, ss, off);
    }
    __shared__ float sh_s[8], sh_ss[8];
    int wid = tid >> 5, lane = tid & 31;
    if (lane == 0) { sh_s[wid] = s; sh_ss[wid] = ss; }
    __syncthreads();
    if (tid == 0) {
        float a = 0.f, c = 0.f;
#pragma unroll
        for (int i = 0; i < 8; i++) { a += sh_s[i]; c += sh_ss[i]; }
        sh_s[0] = a; sh_ss[0] = c;
    }
    __syncthreads();

    float mean = sh_s[0] * (1.f / (float)DM);
    float var  = sh_ss[0] * (1.f / (float)DM) - mean * mean;
    float rstd = rsqrtf(var + LN_EPS);

    out[base + tid]       = (x0 - mean) * rstd * g[tid]       + bb[tid];
    out[base + tid + 256] = (x1 - mean) * rstd * g[tid + 256] + bb[tid + 256];
}

// ---------------------------------------------------------------------------
// Launcher
// ---------------------------------------------------------------------------
extern "C" void kernel_launch(void* const* d_in, const int* in_sizes, int n_in,
                              void* d_out, int out_size)
{
    const float* w    = (const float*)d_in[0];
    const float* r    = (const float*)d_in[1];
    const float* rwb  = (const float*)d_in[2];
    const float* rrb  = (const float*)d_in[3];
    const float* mems = (const float*)d_in[4];
    const float* Wq   = (const float*)d_in[5];
    const float* Wkv  = (const float*)d_in[6];
    const float* Wr   = (const float*)d_in[7];
    const float* Wo   = (const float*)d_in[8];
    const float* lng  = (const float*)d_in[9];
    const float* lnb  = (const float*)d_in[10];
    float* out = (float*)d_out;

    float *kv, *q, *rk, *vec, *ao;
    cudaGetSymbolAddress((void**)&kv,  g_kv);
    cudaGetSymbolAddress((void**)&q,   g_q);
    cudaGetSymbolAddress((void**)&rk,  g_rk);
    cudaGetSymbolAddress((void**)&vec, g_vec);
    cudaGetSymbolAddress((void**)&ao,  g_ao);
    __nv_bfloat16 *axm, *axw, *axr, *axv, *btkv, *btq, *btr, *bto;
    cudaGetSymbolAddress((void**)&axm,  g_ax_mem);
    cudaGetSymbolAddress((void**)&axw,  g_ax_w);
    cudaGetSymbolAddress((void**)&axr,  g_ax_r);
    cudaGetSymbolAddress((void**)&axv,  g_ax_v);
    cudaGetSymbolAddress((void**)&btkv, g_bt_kv);
    cudaGetSymbolAddress((void**)&btq,  g_bt_q);
    cudaGetSymbolAddress((void**)&btr,  g_bt_r);
    cudaGetSymbolAddress((void**)&bto,  g_bt_o);

    cudaFuncSetAttribute(attn_kernel, cudaFuncAttributeMaxDynamicSharedMemorySize,
                         ATTN_SMEM_BYTES);

    // Operand conversions (hi/lo K-extension)
    conv_a_ext<<<2048, 256>>>(mems, axm);                       // M=4096
    conv_a_ext<<<2048, 256>>>(w, axw);                          // M=4096
    conv_a_ext<<<1024, 256>>>(r, axr);                          // M=2048
    conv_bt_ext<<<dim3(32, 16), dim3(32, 8)>>>(Wkv, btkv, 1024);
    conv_bt_ext<<<dim3(16, 16), dim3(32, 8)>>>(Wq,  btq,  512);
    conv_bt_ext<<<dim3(16, 16), dim3(32, 8)>>>(Wr,  btr,  512);
    conv_bt_ext<<<dim3(16, 16), dim3(32, 8)>>>(Wo,  bto,  512);

    // Projection GEMMs on tensor cores (HMMA)
    hgemm<<<dim3(8, 32), 256>>>(axm, btkv, kv, 4096, 1024);
    hgemm<<<dim3(8, 32), 256>>>(axw, btkv, kv + (size_t)4096 * 1024, 4096, 1024);
    hgemm<<<dim3(4, 32), 256>>>(axw, btq, q, 4096, 512);
    hgemm<<<dim3(4, 16), 256>>>(axr, btr, rk, 2048, 512);

    // fused attention (fp32)
    attn_kernel<<<dim3(QLEN / 64, BSZ * NH), 256, ATTN_SMEM_BYTES>>>(q, kv, rk, rwb, rrb, vec);

    // attn_out = vec @ Wo (tensor cores)
    conv_a_ext<<<2048, 256>>>(vec, axv);
    hgemm<<<dim3(4, 32), 256>>>(axv, bto, ao, 4096, 512);

    // residual + layernorm -> d_out
    ln_kernel<<<QLEN * BSZ, 256>>>(w, ao, lng, lnb, out);
}

// round 10
// speedup vs baseline: 1.5512x; 1.3902x over previous
#include <cuda_runtime.h>
#include <cuda_bf16.h>
#include <mma.h>
#include <cstdint>

using namespace nvcuda;

// Problem constants
#define QLEN 1024
#define MLEN 1024
#define KLEN 2048   // QLEN + MLEN
#define BSZ  4
#define NH   8
#define DH   64
#define DM   512    // NH*DH
#define SCALE 0.125f
#define LN_EPS 1e-5f
#define KE   1536   // extended K (hi | lo | hi)

// ---------------------------------------------------------------------------
// Scratch (device globals; allocation inside kernel_launch is forbidden)
// ---------------------------------------------------------------------------
__device__ float g_kv [ (size_t)KLEN * BSZ * 2 * DM ];  // [klen*bsz, 1024] (k | v)
__device__ float g_q  [ (size_t)QLEN * BSZ * DM ];
__device__ float g_rk [ (size_t)KLEN * DM ];
__device__ float g_vec[ (size_t)QLEN * BSZ * DM ];
__device__ float g_ao [ (size_t)QLEN * BSZ * DM ];

// Extended bf16 operands (K' = 1536): A rows = [hi | lo | hi]
__device__ __nv_bfloat16 g_ax_mem[(size_t)4096 * KE];
__device__ __nv_bfloat16 g_ax_w  [(size_t)4096 * KE];
__device__ __nv_bfloat16 g_ax_r  [(size_t)2048 * KE];
__device__ __nv_bfloat16 g_ax_v  [(size_t)4096 * KE];
// Transposed extended weights: Bt rows = [hi | hi | lo]
__device__ __nv_bfloat16 g_bt_kv [(size_t)1024 * KE];
__device__ __nv_bfloat16 g_bt_q  [(size_t)512 * KE];
__device__ __nv_bfloat16 g_bt_r  [(size_t)512 * KE];
__device__ __nv_bfloat16 g_bt_o  [(size_t)512 * KE];

// ---------------------------------------------------------------------------
// Small helpers
// ---------------------------------------------------------------------------
__device__ __forceinline__ uint32_t pack_bf2(float a, float b) {
    __nv_bfloat162 t;
    t.x = __float2bfloat16_rn(a);
    t.y = __float2bfloat16_rn(b);
    return *reinterpret_cast<uint32_t*>(&t);
}
__device__ __forceinline__ void cp16(uint32_t dst, const void* src) {
    asm volatile("cp.async.cg.shared.global [%0], [%1], 16;" :: "r"(dst), "l"(src));
}
__device__ __forceinline__ void cp_commit() {
    asm volatile("cp.async.commit_group;" ::: "memory");
}
template<int N> __device__ __forceinline__ void cp_wait() {
    asm volatile("cp.async.wait_group %0;" :: "n"(N) : "memory");
}
// Split a float4 into hi/lo bf16 quads and store (8B each).
__device__ __forceinline__ void split_store(__nv_bfloat16* hi, __nv_bfloat16* lo,
                                            int off, float4 v) {
    __nv_bfloat16 h0 = __float2bfloat16_rn(v.x), h1 = __float2bfloat16_rn(v.y);
    __nv_bfloat16 h2 = __float2bfloat16_rn(v.z), h3 = __float2bfloat16_rn(v.w);
    uint2 H, L;
    { __nv_bfloat162 t; t.x = h0; t.y = h1; H.x = *(uint32_t*)&t; }
    { __nv_bfloat162 t; t.x = h2; t.y = h3; H.y = *(uint32_t*)&t; }
    L.x = pack_bf2(v.x - __bfloat162float(h0), v.y - __bfloat162float(h1));
    L.y = pack_bf2(v.z - __bfloat162float(h2), v.w - __bfloat162float(h3));
    *(uint2*)(hi + off) = H;
    *(uint2*)(lo + off) = L;
}

// ---------------------------------------------------------------------------
// A-side conversion: A fp32 [M][512] -> Aext bf16 [M][1536] = [hi | lo | hi]
// ---------------------------------------------------------------------------
__global__ __launch_bounds__(256) void conv_a_ext(
    const float* __restrict__ A, __nv_bfloat16* __restrict__ out)
{
    int idx = blockIdx.x * 256 + threadIdx.x;
    int m = idx >> 7;
    int kg = (idx & 127) * 4;
    float4 v = *(const float4*)(A + (size_t)m * 512 + kg);
    __nv_bfloat16 h0 = __float2bfloat16_rn(v.x), h1 = __float2bfloat16_rn(v.y);
    __nv_bfloat16 h2 = __float2bfloat16_rn(v.z), h3 = __float2bfloat16_rn(v.w);
    uint2 HH, LL;
    { __nv_bfloat162 t; t.x = h0; t.y = h1; HH.x = *(uint32_t*)&t; }
    { __nv_bfloat162 t; t.x = h2; t.y = h3; HH.y = *(uint32_t*)&t; }
    LL.x = pack_bf2(v.x - __bfloat162float(h0), v.y - __bfloat162float(h1));
    LL.y = pack_bf2(v.z - __bfloat162float(h2), v.w - __bfloat162float(h3));
    __nv_bfloat16* row = out + (size_t)m * KE;
    *(uint2*)(row + kg)        = HH;
    *(uint2*)(row + 512 + kg)  = LL;
    *(uint2*)(row + 1024 + kg) = HH;
}

// ---------------------------------------------------------------------------
// Weight transpose + extend: W fp32 [512][N] -> Bt bf16 [N][1536] = [hi|hi|lo]
// ---------------------------------------------------------------------------
__global__ __launch_bounds__(256) void conv_bt_ext(
    const float* __restrict__ W, __nv_bfloat16* __restrict__ bt, int N)
{
    __shared__ float t[32][33];
    const int n0 = blockIdx.x * 32, k0 = blockIdx.y * 32;
    const int tx = threadIdx.x, ty = threadIdx.y;
#pragma unroll
    for (int r = 0; r < 32; r += 8)
        t[ty + r][tx] = W[(size_t)(k0 + ty + r) * N + n0 + tx];
    __syncthreads();
#pragma unroll
    for (int r = 0; r < 32; r += 8) {
        float x = t[tx][ty + r];
        __nv_bfloat16 h = __float2bfloat16_rn(x);
        __nv_bfloat16 l = __float2bfloat16_rn(x - __bfloat162float(h));
        __nv_bfloat16* row = bt + (size_t)(n0 + ty + r) * KE;
        row[k0 + tx]        = h;
        row[512 + k0 + tx]  = h;
        row[1024 + k0 + tx] = l;
    }
}

// ---------------------------------------------------------------------------
// bf16 WMMA GEMM: C[M,N] fp32 = Aext[M,KE] @ Bt[N,KE]^T (unchanged from R9)
// ---------------------------------------------------------------------------
#define LDT 40

__global__ __launch_bounds__(256) void hgemm(
    const __nv_bfloat16* __restrict__ A,
    const __nv_bfloat16* __restrict__ Bt,
    float* __restrict__ C, int M, int N)
{
    __shared__ __nv_bfloat16 As[2][128 * LDT];
    __shared__ __nv_bfloat16 Bs[2][128 * LDT];

    const int tid = threadIdx.x;
    const int wid = tid >> 5;
    const int m0 = blockIdx.y * 128, n0 = blockIdx.x * 128;
    const int wm = (wid >> 1) * 32;
    const int wn = (wid & 1) * 64;

    const uint32_t as0 = (uint32_t)__cvta_generic_to_shared(&As[0][0]);
    const uint32_t as1 = (uint32_t)__cvta_generic_to_shared(&As[1][0]);
    const uint32_t bs0 = (uint32_t)__cvta_generic_to_shared(&Bs[0][0]);
    const uint32_t bs1 = (uint32_t)__cvta_generic_to_shared(&Bs[1][0]);

    wmma::fragment<wmma::accumulator, 16, 16, 16, float> cf[2][4];
#pragma unroll
    for (int i = 0; i < 2; i++)
#pragma unroll
        for (int j = 0; j < 4; j++) wmma::fill_fragment(cf[i][j], 0.f);

    auto load_stage = [&](int s, int kc) {
        uint32_t ab = s ? as1 : as0;
        uint32_t bb = s ? bs1 : bs0;
#pragma unroll
        for (int rep = 0; rep < 2; rep++) {
            int chunk = tid + rep * 256;
            int row = chunk >> 2;
            int c = (chunk & 3) * 8;
            cp16(ab + (uint32_t)(row * LDT + c) * 2,
                 A + (size_t)(m0 + row) * KE + kc + c);
            cp16(bb + (uint32_t)(row * LDT + c) * 2,
                 Bt + (size_t)(n0 + row) * KE + kc + c);
        }
    };

    load_stage(0, 0);
    cp_commit();

    const int NKC = KE / 32;
    for (int kc = 0; kc < NKC; kc++) {
        int cur = kc & 1;
        if (kc + 1 < NKC) {
            load_stage(cur ^ 1, (kc + 1) * 32);
            cp_commit();
            cp_wait<1>();
        } else {
            cp_wait<0>();
        }
        __syncthreads();

#pragma unroll
        for (int kk = 0; kk < 32; kk += 16) {
            wmma::fragment<wmma::matrix_a, 16, 16, 16, __nv_bfloat16, wmma::row_major> af[2];
            wmma::fragment<wmma::matrix_b, 16, 16, 16, __nv_bfloat16, wmma::col_major> bf[4];
#pragma unroll
            for (int i = 0; i < 2; i++)
                wmma::load_matrix_sync(af[i], &As[cur][(wm + i * 16) * LDT + kk], LDT);
#pragma unroll
            for (int j = 0; j < 4; j++)
                wmma::load_matrix_sync(bf[j], &Bs[cur][(wn + j * 16) * LDT + kk], LDT);
#pragma unroll
            for (int i = 0; i < 2; i++)
#pragma unroll
                for (int j = 0; j < 4; j++)
                    wmma::mma_sync(cf[i][j], af[i], bf[j], cf[i][j]);
        }
        __syncthreads();
    }

#pragma unroll
    for (int i = 0; i < 2; i++)
#pragma unroll
        for (int j = 0; j < 4; j++)
            wmma::store_matrix_sync(C + (size_t)(m0 + wm + i * 16) * N + n0 + wn + j * 16,
                                    cf[i][j], N, wmma::mem_row_major);
}

// ---------------------------------------------------------------------------
// WMMA flash attention with Transformer-XL relative bias.
//   AC = Qw_ext @ K_ext^T (64x64), G = Qr_ext @ RKwin_ext^T (64x128, skew band),
//   softmax fp32, PV = P_ext @ V_ext (3-term), O rescale in registers.
// Grid (16, 32), 256 threads / 8 warps. Dynamic smem 197632 B.
// ---------------------------------------------------------------------------
#define LDB 72    // bf16 tile stride (elems)
#define LDF 68    // fp32 AC/PVt stride
#define LDG 132   // fp32 G stride
#define ATTN_SMEM_BYTES 197632

__global__ __launch_bounds__(256) void attn_kernel(
    const float* __restrict__ qb, const float* __restrict__ kvb,
    const float* __restrict__ rkb, const float* __restrict__ rwb,
    const float* __restrict__ rrb, float* __restrict__ vec)
{
    extern __shared__ __align__(16) char smem[];
    __nv_bfloat16* bs = (__nv_bfloat16*)smem;
    __nv_bfloat16* qwh = bs;
    __nv_bfloat16* qwl = bs + 1 * 64 * LDB;
    __nv_bfloat16* qrh = bs + 2 * 64 * LDB;
    __nv_bfloat16* qrl = bs + 3 * 64 * LDB;
    __nv_bfloat16* kh  = bs + 4 * 64 * LDB;
    __nv_bfloat16* kl  = bs + 5 * 64 * LDB;
    __nv_bfloat16* vh  = bs + 6 * 64 * LDB;
    __nv_bfloat16* vl  = bs + 7 * 64 * LDB;
    __nv_bfloat16* ph  = bs + 8 * 64 * LDB;
    __nv_bfloat16* pl  = bs + 9 * 64 * LDB;
    __nv_bfloat16* rh[2] = { bs + 10 * 64 * LDB, bs + 12 * 64 * LDB };
    __nv_bfloat16* rl[2] = { bs + 11 * 64 * LDB, bs + 13 * 64 * LDB };
    float* AC  = (float*)(smem + 14 * 64 * LDB * 2);
    float* G   = AC + 64 * LDF;
    float* PVt = G + 64 * LDG;

    const int tid = threadIdx.x;
    const int wid = tid >> 5;
    const int tx = tid & 15;
    const int ty = tid >> 4;
    const int bn = blockIdx.y;
    const int b = bn >> 3;
    const int n = bn & 7;
    const int ib = 15 - blockIdx.x;      // longest CTAs first
    const int i0 = ib * 64;
    const int iw = ty * 4;
    const int jc = tx * 4;
    const int h0 = 15 - ib;              // first rk half index
    const int ntiles = ib + 17;

    const int fi = wid >> 1;             // warp frag row (0..3)

    // ---- prologue: Q tiles (+rwb / +rrb, hi/lo) and rk lower half ----
#pragma unroll
    for (int u = 0; u < 4; u++) {
        int it = tid + u * 256;
        int row = it >> 4, cg = (it & 15) * 4;
        float4 qv = *(const float4*)(qb + (size_t)((i0 + row) * BSZ + b) * DM + n * DH + cg);
        float4 wv = *(const float4*)(rwb + n * DH + cg);
        float4 rv = *(const float4*)(rrb + n * DH + cg);
        split_store(qwh, qwl, row * LDB + cg,
                    make_float4(qv.x + wv.x, qv.y + wv.y, qv.z + wv.z, qv.w + wv.w));
        split_store(qrh, qrl, row * LDB + cg,
                    make_float4(qv.x + rv.x, qv.y + rv.y, qv.z + rv.z, qv.w + rv.w));
    }
#pragma unroll
    for (int u = 0; u < 4; u++) {
        int it = tid + u * 256;
        int row = it >> 4, cg = (it & 15) * 4;
        int d = h0 * 64 + row;
        float4 rv = *(const float4*)(rkb + (size_t)d * DM + n * DH + cg);
        split_store(rh[h0 & 1], rl[h0 & 1], row * LDB + cg, rv);
    }
    __syncthreads();

    float m[4], l[4], o[4][4];
#pragma unroll
    for (int i = 0; i < 4; i++) {
        m[i] = -1e30f; l[i] = 0.f;
#pragma unroll
        for (int j = 0; j < 4; j++) o[i][j] = 0.f;
    }

    for (int t = 0; t < ntiles; t++) {
        const int j0 = t * 64;
        const int hb = h0 + t;           // lower half index of this window
        const int hu = hb + 1;           // upper half to load
        // ---- loads: K, V, new rk half (fp32 -> bf16 hi/lo) ----
#pragma unroll
        for (int u = 0; u < 4; u++) {
            int it = tid + u * 256;
            int row = it >> 4, cg = (it & 15) * 4;
            size_t base = (size_t)((j0 + row) * BSZ + b) * (2 * DM) + n * DH + cg;
            split_store(kh, kl, row * LDB + cg, *(const float4*)(kvb + base));
            split_store(vh, vl, row * LDB + cg, *(const float4*)(kvb + base + DM));
        }
#pragma unroll
        for (int u = 0; u < 4; u++) {
            int it = tid + u * 256;
            int row = it >> 4, cg = (it & 15) * 4;
            int d = hu * 64 + row;
            float4 rv = make_float4(0.f, 0.f, 0.f, 0.f);
            if (d < KLEN) rv = *(const float4*)(rkb + (size_t)d * DM + n * DH + cg);
            split_store(rh[hu & 1], rl[hu & 1], row * LDB + cg, rv);
        }
        __syncthreads();

        // ---- WMMA: AC (64x64) and G (64x128), 3-term hi/lo ----
        {
            wmma::fragment<wmma::accumulator, 16, 16, 16, float> acc[2];
            wmma::fill_fragment(acc[0], 0.f);
            wmma::fill_fragment(acc[1], 0.f);
#pragma unroll
            for (int k = 0; k < 4; k++) {
                int k16 = k * 16;
                wmma::fragment<wmma::matrix_a, 16, 16, 16, __nv_bfloat16, wmma::row_major> ah, al;
                wmma::load_matrix_sync(ah, qwh + fi * 16 * LDB + k16, LDB);
                wmma::load_matrix_sync(al, qwl + fi * 16 * LDB + k16, LDB);
#pragma unroll
                for (int q = 0; q < 2; q++) {
                    int fj = (wid & 1) * 2 + q;
                    wmma::fragment<wmma::matrix_b, 16, 16, 16, __nv_bfloat16, wmma::col_major> bh, bl;
                    wmma::load_matrix_sync(bh, kh + fj * 16 * LDB + k16, LDB);
                    wmma::load_matrix_sync(bl, kl + fj * 16 * LDB + k16, LDB);
                    wmma::mma_sync(acc[q], ah, bh, acc[q]);
                    wmma::mma_sync(acc[q], al, bh, acc[q]);
                    wmma::mma_sync(acc[q], ah, bl, acc[q]);
                }
            }
#pragma unroll
            for (int q = 0; q < 2; q++) {
                int fj = (wid & 1) * 2 + q;
                wmma::store_matrix_sync(AC + fi * 16 * LDF + fj * 16, acc[q], LDF,
                                        wmma::mem_row_major);
            }
        }
        {
            wmma::fragment<wmma::accumulator, 16, 16, 16, float> acc[4];
#pragma unroll
            for (int q = 0; q < 4; q++) wmma::fill_fragment(acc[q], 0.f);
#pragma unroll
            for (int k = 0; k < 4; k++) {
                int k16 = k * 16;
                wmma::fragment<wmma::matrix_a, 16, 16, 16, __nv_bfloat16, wmma::row_major> ah, al;
                wmma::load_matrix_sync(ah, qrh + fi * 16 * LDB + k16, LDB);
                wmma::load_matrix_sync(al, qrl + fi * 16 * LDB + k16, LDB);
#pragma unroll
                for (int q = 0; q < 4; q++) {
                    int fjg = (wid & 1) * 4 + q;          // 0..7 over 128 cols
                    int slot = (hb + (fjg >> 2)) & 1;
                    int rbase = (fjg & 3) * 16 * LDB;
                    wmma::fragment<wmma::matrix_b, 16, 16, 16, __nv_bfloat16, wmma::col_major> bh, bl;
                    wmma::load_matrix_sync(bh, rh[slot] + rbase + k16, LDB);
                    wmma::load_matrix_sync(bl, rl[slot] + rbase + k16, LDB);
                    wmma::mma_sync(acc[q], ah, bh, acc[q]);
                    wmma::mma_sync(acc[q], al, bh, acc[q]);
                    wmma::mma_sync(acc[q], ah, bl, acc[q]);
                }
            }
#pragma unroll
            for (int q = 0; q < 4; q++) {
                int fjg = (wid & 1) * 4 + q;
                wmma::store_matrix_sync(G + fi * 16 * LDG + fjg * 16, acc[q], LDG,
                                        wmma::mem_row_major);
            }
        }
        __syncthreads();

        // ---- softmax (fp32) + P hi/lo write + O rescale ----
#pragma unroll
        for (int ii = 0; ii < 4; ii++) {
            const int ig = i0 + iw + ii;
            float s[4];
            float mx = -1e30f;
#pragma unroll
            for (int jj = 0; jj < 4; jj++) {
                int jg = j0 + jc + jj;
                float v = (AC[(iw + ii) * LDF + jc + jj]
                         + G[(iw + ii) * LDG + (jc + jj) - (iw + ii) + 63]) * SCALE;
                if (jg > ig + MLEN) v = -1e30f;
                s[jj] = v;
                mx = fmaxf(mx, v);
            }
#pragma unroll
            for (int off = 8; off >= 1; off >>= 1)
                mx = fmaxf(mx, __shfl_xor_sync(0xffffffffu, mx, off));
            float mnew = fmaxf(m[ii], mx);
            float f = __expf(m[ii] - mnew);
            float rs = 0.f;
#pragma unroll
            for (int jj = 0; jj < 4; jj++) {
                float p = __expf(s[jj] - mnew);
                __nv_bfloat16 hp = __float2bfloat16_rn(p);
                ph[(iw + ii) * LDB + jc + jj] = hp;
                pl[(iw + ii) * LDB + jc + jj] = __float2bfloat16_rn(p - __bfloat162float(hp));
                rs += p;
            }
#pragma unroll
            for (int off = 8; off >= 1; off >>= 1)
                rs += __shfl_xor_sync(0xffffffffu, rs, off);
            l[ii] = l[ii] * f + rs;
            m[ii] = mnew;
#pragma unroll
            for (int kk = 0; kk < 4; kk++) o[ii][kk] *= f;
        }
        __syncthreads();

        // ---- WMMA PV (3-term) into PVt ----
        {
            wmma::fragment<wmma::accumulator, 16, 16, 16, float> acc[2];
            wmma::fill_fragment(acc[0], 0.f);
            wmma::fill_fragment(acc[1], 0.f);
#pragma unroll
            for (int k = 0; k < 4; k++) {
                int k16 = k * 16;
                wmma::fragment<wmma::matrix_a, 16, 16, 16, __nv_bfloat16, wmma::row_major> ah, al;
                wmma::load_matrix_sync(ah, ph + fi * 16 * LDB + k16, LDB);
                wmma::load_matrix_sync(al, pl + fi * 16 * LDB + k16, LDB);
#pragma unroll
                for (int q = 0; q < 2; q++) {
                    int fj = (wid & 1) * 2 + q;
                    wmma::fragment<wmma::matrix_b, 16, 16, 16, __nv_bfloat16, wmma::row_major> bh, bl;
                    wmma::load_matrix_sync(bh, vh + k16 * LDB + fj * 16, LDB);
                    wmma::load_matrix_sync(bl, vl + k16 * LDB + fj * 16, LDB);
                    wmma::mma_sync(acc[q], ah, bh, acc[q]);
                    wmma::mma_sync(acc[q], al, bh, acc[q]);
                    wmma::mma_sync(acc[q], ah, bl, acc[q]);
                }
            }
#pragma unroll
            for (int q = 0; q < 2; q++) {
                int fj = (wid & 1) * 2 + q;
                wmma::store_matrix_sync(PVt + fi * 16 * LDF + fj * 16, acc[q], LDF,
                                        wmma::mem_row_major);
            }
        }
        __syncthreads();

        // ---- O += PVt ----
#pragma unroll
        for (int ii = 0; ii < 4; ii++)
#pragma unroll
            for (int kk = 0; kk < 4; kk++)
                o[ii][kk] += PVt[(iw + ii) * LDF + jc + kk];
    }

    // ---- epilogue ----
#pragma unroll
    for (int ii = 0; ii < 4; ii++) {
        float inv = 1.f / l[ii];
        float4 v = make_float4(o[ii][0] * inv, o[ii][1] * inv,
                               o[ii][2] * inv, o[ii][3] * inv);
        *(float4*)(vec + (size_t)((i0 + iw + ii) * BSZ + b) * DM + n * DH + jc) = v;
    }
}

// ---------------------------------------------------------------------------
// Residual + LayerNorm (unchanged)
// ---------------------------------------------------------------------------
__global__ __launch_bounds__(256) void ln_kernel(
    const float* __restrict__ w, const float* __restrict__ ao,
    const float* __restrict__ g, const float* __restrict__ bb,
    float* __restrict__ out)
{
    const int row = blockIdx.x;
    const int tid = threadIdx.x;
    const size_t base = (size_t)row * DM;

    float x0 = w[base + tid]       + ao[base + tid];
    float x1 = w[base + tid + 256] + ao[base + tid + 256];
    float s  = x0 + x1;
    float ss = x0 * x0 + x1 * x1;

#pragma unroll
    for (int off = 16; off >= 1; off >>= 1) {
        s  += __shfl_xor_sync(0xffffffffu, s,  off);
        ss += __shfl_xor_sync(0xffffffffu, ss, off);
    }
    __shared__ float sh_s[8], sh_ss[8];
    int wid = tid >> 5, lane = tid & 31;
    if (lane == 0) { sh_s[wid] = s; sh_ss[wid] = ss; }
    __syncthreads();
    if (tid == 0) {
        float a = 0.f, c = 0.f;
#pragma unroll
        for (int i = 0; i < 8; i++) { a += sh_s[i]; c += sh_ss[i]; }
        sh_s[0] = a; sh_ss[0] = c;
    }
    __syncthreads();

    float mean = sh_s[0] * (1.f / (float)DM);
    float var  = sh_ss[0] * (1.f / (float)DM) - mean * mean;
    float rstd = rsqrtf(var + LN_EPS);

    out[base + tid]       = (x0 - mean) * rstd * g[tid]       + bb[tid];
    out[base + tid + 256] = (x1 - mean) * rstd * g[tid + 256] + bb[tid + 256];
}

// ---------------------------------------------------------------------------
// Launcher
// ---------------------------------------------------------------------------
extern "C" void kernel_launch(void* const* d_in, const int* in_sizes, int n_in,
                              void* d_out, int out_size)
{
    const float* w    = (const float*)d_in[0];
    const float* r    = (const float*)d_in[1];
    const float* rwb  = (const float*)d_in[2];
    const float* rrb  = (const float*)d_in[3];
    const float* mems = (const float*)d_in[4];
    const float* Wq   = (const float*)d_in[5];
    const float* Wkv  = (const float*)d_in[6];
    const float* Wr   = (const float*)d_in[7];
    const float* Wo   = (const float*)d_in[8];
    const float* lng  = (const float*)d_in[9];
    const float* lnb  = (const float*)d_in[10];
    float* out = (float*)d_out;

    float *kv, *q, *rk, *vec, *ao;
    cudaGetSymbolAddress((void**)&kv,  g_kv);
    cudaGetSymbolAddress((void**)&q,   g_q);
    cudaGetSymbolAddress((void**)&rk,  g_rk);
    cudaGetSymbolAddress((void**)&vec, g_vec);
    cudaGetSymbolAddress((void**)&ao,  g_ao);
    __nv_bfloat16 *axm, *axw, *axr, *axv, *btkv, *btq, *btr, *bto;
    cudaGetSymbolAddress((void**)&axm,  g_ax_mem);
    cudaGetSymbolAddress((void**)&axw,  g_ax_w);
    cudaGetSymbolAddress((void**)&axr,  g_ax_r);
    cudaGetSymbolAddress((void**)&axv,  g_ax_v);
    cudaGetSymbolAddress((void**)&btkv, g_bt_kv);
    cudaGetSymbolAddress((void**)&btq,  g_bt_q);
    cudaGetSymbolAddress((void**)&btr,  g_bt_r);
    cudaGetSymbolAddress((void**)&bto,  g_bt_o);

    cudaFuncSetAttribute(attn_kernel, cudaFuncAttributeMaxDynamicSharedMemorySize,
                         ATTN_SMEM_BYTES);

    // Operand conversions (hi/lo K-extension)
    conv_a_ext<<<2048, 256>>>(mems, axm);
    conv_a_ext<<<2048, 256>>>(w, axw);
    conv_a_ext<<<1024, 256>>>(r, axr);
    conv_bt_ext<<<dim3(32, 16), dim3(32, 8)>>>(Wkv, btkv, 1024);
    conv_bt_ext<<<dim3(16, 16), dim3(32, 8)>>>(Wq,  btq,  512);
    conv_bt_ext<<<dim3(16, 16), dim3(32, 8)>>>(Wr,  btr,  512);
    conv_bt_ext<<<dim3(16, 16), dim3(32, 8)>>>(Wo,  bto,  512);

    // Projection GEMMs (HMMA)
    hgemm<<<dim3(8, 32), 256>>>(axm, btkv, kv, 4096, 1024);
    hgemm<<<dim3(8, 32), 256>>>(axw, btkv, kv + (size_t)4096 * 1024, 4096, 1024);
    hgemm<<<dim3(4, 32), 256>>>(axw, btq, q, 4096, 512);
    hgemm<<<dim3(4, 16), 256>>>(axr, btr, rk, 2048, 512);

    // WMMA flash attention
    attn_kernel<<<dim3(16, 32), 256, ATTN_SMEM_BYTES>>>(q, kv, rk, rwb, rrb, vec);

    // attn_out = vec @ Wo (HMMA)
    conv_a_ext<<<2048, 256>>>(vec, axv);
    hgemm<<<dim3(4, 32), 256>>>(axv, bto, ao, 4096, 512);

    // residual + layernorm -> d_out
    ln_kernel<<<QLEN * BSZ, 256>>>(w, ao, lng, lnb, out);
}

// round 11
// speedup vs baseline: 1.6656x; 1.0738x over previous
#include <cuda_runtime.h>
#include <cuda_bf16.h>
#include <mma.h>
#include <cstdint>

using namespace nvcuda;

// Problem constants
#define QLEN 1024
#define MLEN 1024
#define KLEN 2048   // QLEN + MLEN
#define BSZ  4
#define NH   8
#define DH   64
#define DM   512    // NH*DH
#define SCALE 0.125f
#define LN_EPS 1e-5f
#define KE   1536   // extended K (hi | lo | hi)

// ---------------------------------------------------------------------------
// Scratch (device globals; allocation inside kernel_launch is forbidden)
// ---------------------------------------------------------------------------
__device__ float g_kv [ (size_t)KLEN * BSZ * 2 * DM ];  // [klen*bsz, 1024] (k | v)
__device__ float g_q  [ (size_t)QLEN * BSZ * DM ];
__device__ float g_rk [ (size_t)KLEN * DM ];
__device__ float g_vec[ (size_t)QLEN * BSZ * DM ];
__device__ float g_ao [ (size_t)QLEN * BSZ * DM ];

// Extended bf16 operands (K' = 1536): A rows = [hi | lo | hi]
__device__ __nv_bfloat16 g_ax_mem[(size_t)4096 * KE];
__device__ __nv_bfloat16 g_ax_w  [(size_t)4096 * KE];
__device__ __nv_bfloat16 g_ax_r  [(size_t)2048 * KE];
__device__ __nv_bfloat16 g_ax_v  [(size_t)4096 * KE];
// Transposed extended weights: Bt rows = [hi | hi | lo]
__device__ __nv_bfloat16 g_bt_kv [(size_t)1024 * KE];
__device__ __nv_bfloat16 g_bt_q  [(size_t)512 * KE];
__device__ __nv_bfloat16 g_bt_r  [(size_t)512 * KE];
__device__ __nv_bfloat16 g_bt_o  [(size_t)512 * KE];

// ---------------------------------------------------------------------------
// Small helpers
// ---------------------------------------------------------------------------
__device__ __forceinline__ uint32_t pack_bf2(float a, float b) {
    __nv_bfloat162 t;
    t.x = __float2bfloat16_rn(a);
    t.y = __float2bfloat16_rn(b);
    return *reinterpret_cast<uint32_t*>(&t);
}
__device__ __forceinline__ void cp16(uint32_t dst, const void* src) {
    asm volatile("cp.async.cg.shared.global [%0], [%1], 16;" :: "r"(dst), "l"(src));
}
__device__ __forceinline__ void cp_commit() {
    asm volatile("cp.async.commit_group;" ::: "memory");
}
template<int N> __device__ __forceinline__ void cp_wait() {
    asm volatile("cp.async.wait_group %0;" :: "n"(N) : "memory");
}
// Split a float4 into hi/lo bf16 quads and store (8B each).
__device__ __forceinline__ void split_store(__nv_bfloat16* hi, __nv_bfloat16* lo,
                                            int off, float4 v) {
    __nv_bfloat16 h0 = __float2bfloat16_rn(v.x), h1 = __float2bfloat16_rn(v.y);
    __nv_bfloat16 h2 = __float2bfloat16_rn(v.z), h3 = __float2bfloat16_rn(v.w);
    uint2 H, L;
    { __nv_bfloat162 t; t.x = h0; t.y = h1; H.x = *(uint32_t*)&t; }
    { __nv_bfloat162 t; t.x = h2; t.y = h3; H.y = *(uint32_t*)&t; }
    L.x = pack_bf2(v.x - __bfloat162float(h0), v.y - __bfloat162float(h1));
    L.y = pack_bf2(v.z - __bfloat162float(h2), v.w - __bfloat162float(h3));
    *(uint2*)(hi + off) = H;
    *(uint2*)(lo + off) = L;
}

// ---------------------------------------------------------------------------
// A-side conversion: A fp32 [M][512] -> Aext bf16 [M][1536] = [hi | lo | hi]
// ---------------------------------------------------------------------------
__global__ __launch_bounds__(256) void conv_a_ext(
    const float* __restrict__ A, __nv_bfloat16* __restrict__ out)
{
    int idx = blockIdx.x * 256 + threadIdx.x;
    int m = idx >> 7;
    int kg = (idx & 127) * 4;
    float4 v = *(const float4*)(A + (size_t)m * 512 + kg);
    __nv_bfloat16 h0 = __float2bfloat16_rn(v.x), h1 = __float2bfloat16_rn(v.y);
    __nv_bfloat16 h2 = __float2bfloat16_rn(v.z), h3 = __float2bfloat16_rn(v.w);
    uint2 HH, LL;
    { __nv_bfloat162 t; t.x = h0; t.y = h1; HH.x = *(uint32_t*)&t; }
    { __nv_bfloat162 t; t.x = h2; t.y = h3; HH.y = *(uint32_t*)&t; }
    LL.x = pack_bf2(v.x - __bfloat162float(h0), v.y - __bfloat162float(h1));
    LL.y = pack_bf2(v.z - __bfloat162float(h2), v.w - __bfloat162float(h3));
    __nv_bfloat16* row = out + (size_t)m * KE;
    *(uint2*)(row + kg)        = HH;
    *(uint2*)(row + 512 + kg)  = LL;
    *(uint2*)(row + 1024 + kg) = HH;
}

// ---------------------------------------------------------------------------
// Weight transpose + extend: W fp32 [512][N] -> Bt bf16 [N][1536] = [hi|hi|lo]
// ---------------------------------------------------------------------------
__global__ __launch_bounds__(256) void conv_bt_ext(
    const float* __restrict__ W, __nv_bfloat16* __restrict__ bt, int N)
{
    __shared__ float t[32][33];
    const int n0 = blockIdx.x * 32, k0 = blockIdx.y * 32;
    const int tx = threadIdx.x, ty = threadIdx.y;
#pragma unroll
    for (int r = 0; r < 32; r += 8)
        t[ty + r][tx] = W[(size_t)(k0 + ty + r) * N + n0 + tx];
    __syncthreads();
#pragma unroll
    for (int r = 0; r < 32; r += 8) {
        float x = t[tx][ty + r];
        __nv_bfloat16 h = __float2bfloat16_rn(x);
        __nv_bfloat16 l = __float2bfloat16_rn(x - __bfloat162float(h));
        __nv_bfloat16* row = bt + (size_t)(n0 + ty + r) * KE;
        row[k0 + tx]        = h;
        row[512 + k0 + tx]  = h;
        row[1024 + k0 + tx] = l;
    }
}

// ---------------------------------------------------------------------------
// bf16 WMMA GEMM v2: C[M,N] fp32 = Aext[M,KE] @ Bt[N,KE]^T
// CTA tile 128x128, 4 warps, warp tile 64x64 (4x4 wmma frags).
// K-chunk 64, cp.async double-buffered. Dynamic smem 73728 B.
// ---------------------------------------------------------------------------
#define LD2 72
#define HG_SMEM (4 * 128 * LD2 * 2)   // 73728 bytes

__global__ __launch_bounds__(128) void hgemm(
    const __nv_bfloat16* __restrict__ A,
    const __nv_bfloat16* __restrict__ Bt,
    float* __restrict__ C, int M, int N)
{
    extern __shared__ __align__(16) __nv_bfloat16 sm2[];
    __nv_bfloat16* Asm[2] = { sm2,                sm2 + 128 * LD2 };
    __nv_bfloat16* Bsm[2] = { sm2 + 2 * 128 * LD2, sm2 + 3 * 128 * LD2 };
    uint32_t asa[2], bsa[2];
#pragma unroll
    for (int s = 0; s < 2; s++) {
        asa[s] = (uint32_t)__cvta_generic_to_shared(Asm[s]);
        bsa[s] = (uint32_t)__cvta_generic_to_shared(Bsm[s]);
    }

    const int tid = threadIdx.x;
    const int wid = tid >> 5;
    const int m0 = blockIdx.y * 128, n0 = blockIdx.x * 128;
    const int wm = (wid >> 1) * 64;   // 0 or 64
    const int wn = (wid & 1) * 64;    // 0 or 64

    wmma::fragment<wmma::accumulator, 16, 16, 16, float> cf[4][4];
#pragma unroll
    for (int i = 0; i < 4; i++)
#pragma unroll
        for (int j = 0; j < 4; j++) wmma::fill_fragment(cf[i][j], 0.f);

    // stage loader: A and B each 128 rows x 64 bf16 (128 B/row = 8 cp16)
    auto load_stage = [&](int s, int kc) {
#pragma unroll
        for (int u = 0; u < 8; u++) {
            int chunk = tid + u * 128;          // 0..1023
            int row = chunk >> 3;
            int c = (chunk & 7) * 8;
            cp16(asa[s] + (uint32_t)(row * LD2 + c) * 2,
                 A + (size_t)(m0 + row) * KE + kc + c);
        }
#pragma unroll
        for (int u = 0; u < 8; u++) {
            int chunk = tid + u * 128;
            int row = chunk >> 3;
            int c = (chunk & 7) * 8;
            cp16(bsa[s] + (uint32_t)(row * LD2 + c) * 2,
                 Bt + (size_t)(n0 + row) * KE + kc + c);
        }
    };

    load_stage(0, 0);
    cp_commit();

    const int NKC = KE / 64;   // 24
    for (int kc = 0; kc < NKC; kc++) {
        int cur = kc & 1;
        if (kc + 1 < NKC) {
            load_stage(cur ^ 1, (kc + 1) * 64);
            cp_commit();
            cp_wait<1>();
        } else {
            cp_wait<0>();
        }
        __syncthreads();

#pragma unroll
        for (int kk = 0; kk < 64; kk += 16) {
            wmma::fragment<wmma::matrix_a, 16, 16, 16, __nv_bfloat16, wmma::row_major> af[4];
            wmma::fragment<wmma::matrix_b, 16, 16, 16, __nv_bfloat16, wmma::col_major> bf[4];
#pragma unroll
            for (int i = 0; i < 4; i++)
                wmma::load_matrix_sync(af[i], Asm[cur] + (wm + i * 16) * LD2 + kk, LD2);
#pragma unroll
            for (int j = 0; j < 4; j++)
                wmma::load_matrix_sync(bf[j], Bsm[cur] + (wn + j * 16) * LD2 + kk, LD2);
#pragma unroll
            for (int i = 0; i < 4; i++)
#pragma unroll
                for (int j = 0; j < 4; j++)
                    wmma::mma_sync(cf[i][j], af[i], bf[j], cf[i][j]);
        }
        __syncthreads();
    }

#pragma unroll
    for (int i = 0; i < 4; i++)
#pragma unroll
        for (int j = 0; j < 4; j++)
            wmma::store_matrix_sync(C + (size_t)(m0 + wm + i * 16) * N + n0 + wn + j * 16,
                                    cf[i][j], N, wmma::mem_row_major);
}

// ---------------------------------------------------------------------------
// WMMA flash attention with Transformer-XL relative bias (unchanged from R10).
// ---------------------------------------------------------------------------
#define LDB 72    // bf16 tile stride (elems)
#define LDF 68    // fp32 AC/PVt stride
#define LDG 132   // fp32 G stride
#define ATTN_SMEM_BYTES 197632

__global__ __launch_bounds__(256) void attn_kernel(
    const float* __restrict__ qb, const float* __restrict__ kvb,
    const float* __restrict__ rkb, const float* __restrict__ rwb,
    const float* __restrict__ rrb, float* __restrict__ vec)
{
    extern __shared__ __align__(16) char smem[];
    __nv_bfloat16* bs = (__nv_bfloat16*)smem;
    __nv_bfloat16* qwh = bs;
    __nv_bfloat16* qwl = bs + 1 * 64 * LDB;
    __nv_bfloat16* qrh = bs + 2 * 64 * LDB;
    __nv_bfloat16* qrl = bs + 3 * 64 * LDB;
    __nv_bfloat16* kh  = bs + 4 * 64 * LDB;
    __nv_bfloat16* kl  = bs + 5 * 64 * LDB;
    __nv_bfloat16* vh  = bs + 6 * 64 * LDB;
    __nv_bfloat16* vl  = bs + 7 * 64 * LDB;
    __nv_bfloat16* ph  = bs + 8 * 64 * LDB;
    __nv_bfloat16* pl  = bs + 9 * 64 * LDB;
    __nv_bfloat16* rh[2] = { bs + 10 * 64 * LDB, bs + 12 * 64 * LDB };
    __nv_bfloat16* rl[2] = { bs + 11 * 64 * LDB, bs + 13 * 64 * LDB };
    float* AC  = (float*)(smem + 14 * 64 * LDB * 2);
    float* G   = AC + 64 * LDF;
    float* PVt = G + 64 * LDG;

    const int tid = threadIdx.x;
    const int wid = tid >> 5;
    const int tx = tid & 15;
    const int ty = tid >> 4;
    const int bn = blockIdx.y;
    const int b = bn >> 3;
    const int n = bn & 7;
    const int ib = 15 - blockIdx.x;      // longest CTAs first
    const int i0 = ib * 64;
    const int iw = ty * 4;
    const int jc = tx * 4;
    const int h0 = 15 - ib;              // first rk half index
    const int ntiles = ib + 17;

    const int fi = wid >> 1;             // warp frag row (0..3)

#pragma unroll
    for (int u = 0; u < 4; u++) {
        int it = tid + u * 256;
        int row = it >> 4, cg = (it & 15) * 4;
        float4 qv = *(const float4*)(qb + (size_t)((i0 + row) * BSZ + b) * DM + n * DH + cg);
        float4 wv = *(const float4*)(rwb + n * DH + cg);
        float4 rv = *(const float4*)(rrb + n * DH + cg);
        split_store(qwh, qwl, row * LDB + cg,
                    make_float4(qv.x + wv.x, qv.y + wv.y, qv.z + wv.z, qv.w + wv.w));
        split_store(qrh, qrl, row * LDB + cg,
                    make_float4(qv.x + rv.x, qv.y + rv.y, qv.z + rv.z, qv.w + rv.w));
    }
#pragma unroll
    for (int u = 0; u < 4; u++) {
        int it = tid + u * 256;
        int row = it >> 4, cg = (it & 15) * 4;
        int d = h0 * 64 + row;
        float4 rv = *(const float4*)(rkb + (size_t)d * DM + n * DH + cg);
        split_store(rh[h0 & 1], rl[h0 & 1], row * LDB + cg, rv);
    }
    __syncthreads();

    float m[4], l[4], o[4][4];
#pragma unroll
    for (int i = 0; i < 4; i++) {
        m[i] = -1e30f; l[i] = 0.f;
#pragma unroll
        for (int j = 0; j < 4; j++) o[i][j] = 0.f;
    }

    for (int t = 0; t < ntiles; t++) {
        const int j0 = t * 64;
        const int hb = h0 + t;
        const int hu = hb + 1;
#pragma unroll
        for (int u = 0; u < 4; u++) {
            int it = tid + u * 256;
            int row = it >> 4, cg = (it & 15) * 4;
            size_t base = (size_t)((j0 + row) * BSZ + b) * (2 * DM) + n * DH + cg;
            split_store(kh, kl, row * LDB + cg, *(const float4*)(kvb + base));
            split_store(vh, vl, row * LDB + cg, *(const float4*)(kvb + base + DM));
        }
#pragma unroll
        for (int u = 0; u < 4; u++) {
            int it = tid + u * 256;
            int row = it >> 4, cg = (it & 15) * 4;
            int d = hu * 64 + row;
            float4 rv = make_float4(0.f, 0.f, 0.f, 0.f);
            if (d < KLEN) rv = *(const float4*)(rkb + (size_t)d * DM + n * DH + cg);
            split_store(rh[hu & 1], rl[hu & 1], row * LDB + cg, rv);
        }
        __syncthreads();

        {
            wmma::fragment<wmma::accumulator, 16, 16, 16, float> acc[2];
            wmma::fill_fragment(acc[0], 0.f);
            wmma::fill_fragment(acc[1], 0.f);
#pragma unroll
            for (int k = 0; k < 4; k++) {
                int k16 = k * 16;
                wmma::fragment<wmma::matrix_a, 16, 16, 16, __nv_bfloat16, wmma::row_major> ah, al;
                wmma::load_matrix_sync(ah, qwh + fi * 16 * LDB + k16, LDB);
                wmma::load_matrix_sync(al, qwl + fi * 16 * LDB + k16, LDB);
#pragma unroll
                for (int q = 0; q < 2; q++) {
                    int fj = (wid & 1) * 2 + q;
                    wmma::fragment<wmma::matrix_b, 16, 16, 16, __nv_bfloat16, wmma::col_major> bh, bl;
                    wmma::load_matrix_sync(bh, kh + fj * 16 * LDB + k16, LDB);
                    wmma::load_matrix_sync(bl, kl + fj * 16 * LDB + k16, LDB);
                    wmma::mma_sync(acc[q], ah, bh, acc[q]);
                    wmma::mma_sync(acc[q], al, bh, acc[q]);
                    wmma::mma_sync(acc[q], ah, bl, acc[q]);
                }
            }
#pragma unroll
            for (int q = 0; q < 2; q++) {
                int fj = (wid & 1) * 2 + q;
                wmma::store_matrix_sync(AC + fi * 16 * LDF + fj * 16, acc[q], LDF,
                                        wmma::mem_row_major);
            }
        }
        {
            wmma::fragment<wmma::accumulator, 16, 16, 16, float> acc[4];
#pragma unroll
            for (int q = 0; q < 4; q++) wmma::fill_fragment(acc[q], 0.f);
#pragma unroll
            for (int k = 0; k < 4; k++) {
                int k16 = k * 16;
                wmma::fragment<wmma::matrix_a, 16, 16, 16, __nv_bfloat16, wmma::row_major> ah, al;
                wmma::load_matrix_sync(ah, qrh + fi * 16 * LDB + k16, LDB);
                wmma::load_matrix_sync(al, qrl + fi * 16 * LDB + k16, LDB);
#pragma unroll
                for (int q = 0; q < 4; q++) {
                    int fjg = (wid & 1) * 4 + q;
                    int slot = (hb + (fjg >> 2)) & 1;
                    int rbase = (fjg & 3) * 16 * LDB;
                    wmma::fragment<wmma::matrix_b, 16, 16, 16, __nv_bfloat16, wmma::col_major> bh, bl;
                    wmma::load_matrix_sync(bh, rh[slot] + rbase + k16, LDB);
                    wmma::load_matrix_sync(bl, rl[slot] + rbase + k16, LDB);
                    wmma::mma_sync(acc[q], ah, bh, acc[q]);
                    wmma::mma_sync(acc[q], al, bh, acc[q]);
                    wmma::mma_sync(acc[q], ah, bl, acc[q]);
                }
            }
#pragma unroll
            for (int q = 0; q < 4; q++) {
                int fjg = (wid & 1) * 4 + q;
                wmma::store_matrix_sync(G + fi * 16 * LDG + fjg * 16, acc[q], LDG,
                                        wmma::mem_row_major);
            }
        }
        __syncthreads();

#pragma unroll
        for (int ii = 0; ii < 4; ii++) {
            const int ig = i0 + iw + ii;
            float s[4];
            float mx = -1e30f;
#pragma unroll
            for (int jj = 0; jj < 4; jj++) {
                int jg = j0 + jc + jj;
                float v = (AC[(iw + ii) * LDF + jc + jj]
                         + G[(iw + ii) * LDG + (jc + jj) - (iw + ii) + 63]) * SCALE;
                if (jg > ig + MLEN) v = -1e30f;
                s[jj] = v;
                mx = fmaxf(mx, v);
            }
#pragma unroll
            for (int off = 8; off >= 1; off >>= 1)
                mx = fmaxf(mx, __shfl_xor_sync(0xffffffffu, mx, off));
            float mnew = fmaxf(m[ii], mx);
            float f = __expf(m[ii] - mnew);
            float rs = 0.f;
#pragma unroll
            for (int jj = 0; jj < 4; jj++) {
                float p = __expf(s[jj] - mnew);
                __nv_bfloat16 hp = __float2bfloat16_rn(p);
                ph[(iw + ii) * LDB + jc + jj] = hp;
                pl[(iw + ii) * LDB + jc + jj] = __float2bfloat16_rn(p - __bfloat162float(hp));
                rs += p;
            }
#pragma unroll
            for (int off = 8; off >= 1; off >>= 1)
                rs += __shfl_xor_sync(0xffffffffu, rs, off);
            l[ii] = l[ii] * f + rs;
            m[ii] = mnew;
#pragma unroll
            for (int kk = 0; kk < 4; kk++) o[ii][kk] *= f;
        }
        __syncthreads();

        {
            wmma::fragment<wmma::accumulator, 16, 16, 16, float> acc[2];
            wmma::fill_fragment(acc[0], 0.f);
            wmma::fill_fragment(acc[1], 0.f);
#pragma unroll
            for (int k = 0; k < 4; k++) {
                int k16 = k * 16;
                wmma::fragment<wmma::matrix_a, 16, 16, 16, __nv_bfloat16, wmma::row_major> ah, al;
                wmma::load_matrix_sync(ah, ph + fi * 16 * LDB + k16, LDB);
                wmma::load_matrix_sync(al, pl + fi * 16 * LDB + k16, LDB);
#pragma unroll
                for (int q = 0; q < 2; q++) {
                    int fj = (wid & 1) * 2 + q;
                    wmma::fragment<wmma::matrix_b, 16, 16, 16, __nv_bfloat16, wmma::row_major> bh, bl;
                    wmma::load_matrix_sync(bh, vh + k16 * LDB + fj * 16, LDB);
                    wmma::load_matrix_sync(bl, vl + k16 * LDB + fj * 16, LDB);
                    wmma::mma_sync(acc[q], ah, bh, acc[q]);
                    wmma::mma_sync(acc[q], al, bh, acc[q]);
                    wmma::mma_sync(acc[q], ah, bl, acc[q]);
                }
            }
#pragma unroll
            for (int q = 0; q < 2; q++) {
                int fj = (wid & 1) * 2 + q;
                wmma::store_matrix_sync(PVt + fi * 16 * LDF + fj * 16, acc[q], LDF,
                                        wmma::mem_row_major);
            }
        }
        __syncthreads();

#pragma unroll
        for (int ii = 0; ii < 4; ii++)
#pragma unroll
            for (int kk = 0; kk < 4; kk++)
                o[ii][kk] += PVt[(iw + ii) * LDF + jc + kk];
    }

#pragma unroll
    for (int ii = 0; ii < 4; ii++) {
        float inv = 1.f / l[ii];
        float4 v = make_float4(o[ii][0] * inv, o[ii][1] * inv,
                               o[ii][2] * inv, o[ii][3] * inv);
        *(float4*)(vec + (size_t)((i0 + iw + ii) * BSZ + b) * DM + n * DH + jc) = v;
    }
}

// ---------------------------------------------------------------------------
// Residual + LayerNorm (unchanged)
// ---------------------------------------------------------------------------
__global__ __launch_bounds__(256) void ln_kernel(
    const float* __restrict__ w, const float* __restrict__ ao,
    const float* __restrict__ g, const float* __restrict__ bb,
    float* __restrict__ out)
{
    const int row = blockIdx.x;
    const int tid = threadIdx.x;
    const size_t base = (size_t)row * DM;

    float x0 = w[base + tid]       + ao[base + tid];
    float x1 = w[base + tid + 256] + ao[base + tid + 256];
    float s  = x0 + x1;
    float ss = x0 * x0 + x1 * x1;

#pragma unroll
    for (int off = 16; off >= 1; off >>= 1) {
        s  += __shfl_xor_sync(0xffffffffu, s,  off);
        ss += __shfl_xor_sync(0xffffffffu, ss, off);
    }
    __shared__ float sh_s[8], sh_ss[8];
    int wid = tid >> 5, lane = tid & 31;
    if (lane == 0) { sh_s[wid] = s; sh_ss[wid] = ss; }
    __syncthreads();
    if (tid == 0) {
        float a = 0.f, c = 0.f;
#pragma unroll
        for (int i = 0; i < 8; i++) { a += sh_s[i]; c += sh_ss[i]; }
        sh_s[0] = a; sh_ss[0] = c;
    }
    __syncthreads();

    float mean = sh_s[0] * (1.f / (float)DM);
    float var  = sh_ss[0] * (1.f / (float)DM) - mean * mean;
    float rstd = rsqrtf(var + LN_EPS);

    out[base + tid]       = (x0 - mean) * rstd * g[tid]       + bb[tid];
    out[base + tid + 256] = (x1 - mean) * rstd * g[tid + 256] + bb[tid + 256];
}

// ---------------------------------------------------------------------------
// Launcher
// ---------------------------------------------------------------------------
extern "C" void kernel_launch(void* const* d_in, const int* in_sizes, int n_in,
                              void* d_out, int out_size)
{
    const float* w    = (const float*)d_in[0];
    const float* r    = (const float*)d_in[1];
    const float* rwb  = (const float*)d_in[2];
    const float* rrb  = (const float*)d_in[3];
    const float* mems = (const float*)d_in[4];
    const float* Wq   = (const float*)d_in[5];
    const float* Wkv  = (const float*)d_in[6];
    const float* Wr   = (const float*)d_in[7];
    const float* Wo   = (const float*)d_in[8];
    const float* lng  = (const float*)d_in[9];
    const float* lnb  = (const float*)d_in[10];
    float* out = (float*)d_out;

    float *kv, *q, *rk, *vec, *ao;
    cudaGetSymbolAddress((void**)&kv,  g_kv);
    cudaGetSymbolAddress((void**)&q,   g_q);
    cudaGetSymbolAddress((void**)&rk,  g_rk);
    cudaGetSymbolAddress((void**)&vec, g_vec);
    cudaGetSymbolAddress((void**)&ao,  g_ao);
    __nv_bfloat16 *axm, *axw, *axr, *axv, *btkv, *btq, *btr, *bto;
    cudaGetSymbolAddress((void**)&axm,  g_ax_mem);
    cudaGetSymbolAddress((void**)&axw,  g_ax_w);
    cudaGetSymbolAddress((void**)&axr,  g_ax_r);
    cudaGetSymbolAddress((void**)&axv,  g_ax_v);
    cudaGetSymbolAddress((void**)&btkv, g_bt_kv);
    cudaGetSymbolAddress((void**)&btq,  g_bt_q);
    cudaGetSymbolAddress((void**)&btr,  g_bt_r);
    cudaGetSymbolAddress((void**)&bto,  g_bt_o);

    cudaFuncSetAttribute(attn_kernel, cudaFuncAttributeMaxDynamicSharedMemorySize,
                         ATTN_SMEM_BYTES);
    cudaFuncSetAttribute(hgemm, cudaFuncAttributeMaxDynamicSharedMemorySize, HG_SMEM);

    // Operand conversions (hi/lo K-extension)
    conv_a_ext<<<2048, 256>>>(mems, axm);
    conv_a_ext<<<2048, 256>>>(w, axw);
    conv_a_ext<<<1024, 256>>>(r, axr);
    conv_bt_ext<<<dim3(32, 16), dim3(32, 8)>>>(Wkv, btkv, 1024);
    conv_bt_ext<<<dim3(16, 16), dim3(32, 8)>>>(Wq,  btq,  512);
    conv_bt_ext<<<dim3(16, 16), dim3(32, 8)>>>(Wr,  btr,  512);
    conv_bt_ext<<<dim3(16, 16), dim3(32, 8)>>>(Wo,  bto,  512);

    // Projection GEMMs (HMMA)
    hgemm<<<dim3(8, 32), 128, HG_SMEM>>>(axm, btkv, kv, 4096, 1024);
    hgemm<<<dim3(8, 32), 128, HG_SMEM>>>(axw, btkv, kv + (size_t)4096 * 1024, 4096, 1024);
    hgemm<<<dim3(4, 32), 128, HG_SMEM>>>(axw, btq, q, 4096, 512);
    hgemm<<<dim3(4, 16), 128, HG_SMEM>>>(axr, btr, rk, 2048, 512);

    // WMMA flash attention
    attn_kernel<<<dim3(16, 32), 256, ATTN_SMEM_BYTES>>>(q, kv, rk, rwb, rrb, vec);

    // attn_out = vec @ Wo (HMMA)
    conv_a_ext<<<2048, 256>>>(vec, axv);
    hgemm<<<dim3(4, 32), 256 / 2, HG_SMEM>>>(axv, bto, ao, 4096, 512);

    // residual + layernorm -> d_out
    ln_kernel<<<QLEN * BSZ, 256>>>(w, ao, lng, lnb, out);
}

// round 12
// speedup vs baseline: 1.7331x; 1.0405x over previous
#include <cuda_runtime.h>
#include <cuda_bf16.h>
#include <mma.h>
#include <cstdint>

using namespace nvcuda;

// Problem constants
#define QLEN 1024
#define MLEN 1024
#define KLEN 2048   // QLEN + MLEN
#define BSZ  4
#define NH   8
#define DH   64
#define DM   512    // NH*DH
#define SCALE 0.125f
#define LN_EPS 1e-5f
#define KE   1536   // extended K (hi | lo | hi)

// ---------------------------------------------------------------------------
// Scratch (device globals; allocation inside kernel_launch is forbidden)
// ---------------------------------------------------------------------------
__device__ float g_q  [ (size_t)QLEN * BSZ * DM ];
__device__ float g_vec[ (size_t)QLEN * BSZ * DM ];
__device__ float g_ao [ (size_t)QLEN * BSZ * DM ];

// kv / rk stored directly as bf16 hi/lo (written by hgemm<1> epilogue)
__device__ __nv_bfloat16 g_kvh[(size_t)KLEN * BSZ * 2 * DM];
__device__ __nv_bfloat16 g_kvl[(size_t)KLEN * BSZ * 2 * DM];
__device__ __nv_bfloat16 g_rkh[(size_t)KLEN * DM];
__device__ __nv_bfloat16 g_rkl[(size_t)KLEN * DM];

// Extended bf16 operands (K' = 1536): A rows = [hi | lo | hi]
__device__ __nv_bfloat16 g_ax_mem[(size_t)4096 * KE];
__device__ __nv_bfloat16 g_ax_w  [(size_t)4096 * KE];
__device__ __nv_bfloat16 g_ax_r  [(size_t)2048 * KE];
__device__ __nv_bfloat16 g_ax_v  [(size_t)4096 * KE];
// Transposed extended weights: Bt rows = [hi | hi | lo]
__device__ __nv_bfloat16 g_bt_kv [(size_t)1024 * KE];
__device__ __nv_bfloat16 g_bt_q  [(size_t)512 * KE];
__device__ __nv_bfloat16 g_bt_r  [(size_t)512 * KE];
__device__ __nv_bfloat16 g_bt_o  [(size_t)512 * KE];

// ---------------------------------------------------------------------------
// Small helpers
// ---------------------------------------------------------------------------
__device__ __forceinline__ uint32_t pack_bf2(float a, float b) {
    __nv_bfloat162 t;
    t.x = __float2bfloat16_rn(a);
    t.y = __float2bfloat16_rn(b);
    return *reinterpret_cast<uint32_t*>(&t);
}
__device__ __forceinline__ void cp16(uint32_t dst, const void* src) {
    asm volatile("cp.async.cg.shared.global [%0], [%1], 16;" :: "r"(dst), "l"(src));
}
// cp.async with runtime src-size (0 => zero-fill)
__device__ __forceinline__ void cp16z(uint32_t dst, const void* src, int sz) {
    asm volatile("cp.async.cg.shared.global [%0], [%1], 16, %2;"
                 :: "r"(dst), "l"(src), "r"(sz));
}
__device__ __forceinline__ void cp_commit() {
    asm volatile("cp.async.commit_group;" ::: "memory");
}
template<int N> __device__ __forceinline__ void cp_wait() {
    asm volatile("cp.async.wait_group %0;" :: "n"(N) : "memory");
}
// Split a float4 into hi/lo bf16 quads and store (8B each).
__device__ __forceinline__ void split_store(__nv_bfloat16* hi, __nv_bfloat16* lo,
                                            size_t off, float4 v) {
    __nv_bfloat16 h0 = __float2bfloat16_rn(v.x), h1 = __float2bfloat16_rn(v.y);
    __nv_bfloat16 h2 = __float2bfloat16_rn(v.z), h3 = __float2bfloat16_rn(v.w);
    uint2 H, L;
    { __nv_bfloat162 t; t.x = h0; t.y = h1; H.x = *(uint32_t*)&t; }
    { __nv_bfloat162 t; t.x = h2; t.y = h3; H.y = *(uint32_t*)&t; }
    L.x = pack_bf2(v.x - __bfloat162float(h0), v.y - __bfloat162float(h1));
    L.y = pack_bf2(v.z - __bfloat162float(h2), v.w - __bfloat162float(h3));
    *(uint2*)(hi + off) = H;
    *(uint2*)(lo + off) = L;
}

// ---------------------------------------------------------------------------
// A-side conversion: A fp32 [M][512] -> Aext bf16 [M][1536] = [hi | lo | hi]
// ---------------------------------------------------------------------------
__global__ __launch_bounds__(256) void conv_a_ext(
    const float* __restrict__ A, __nv_bfloat16* __restrict__ out)
{
    int idx = blockIdx.x * 256 + threadIdx.x;
    int m = idx >> 7;
    int kg = (idx & 127) * 4;
    float4 v = *(const float4*)(A + (size_t)m * 512 + kg);
    __nv_bfloat16 h0 = __float2bfloat16_rn(v.x), h1 = __float2bfloat16_rn(v.y);
    __nv_bfloat16 h2 = __float2bfloat16_rn(v.z), h3 = __float2bfloat16_rn(v.w);
    uint2 HH, LL;
    { __nv_bfloat162 t; t.x = h0; t.y = h1; HH.x = *(uint32_t*)&t; }
    { __nv_bfloat162 t; t.x = h2; t.y = h3; HH.y = *(uint32_t*)&t; }
    LL.x = pack_bf2(v.x - __bfloat162float(h0), v.y - __bfloat162float(h1));
    LL.y = pack_bf2(v.z - __bfloat162float(h2), v.w - __bfloat162float(h3));
    __nv_bfloat16* row = out + (size_t)m * KE;
    *(uint2*)(row + kg)        = HH;
    *(uint2*)(row + 512 + kg)  = LL;
    *(uint2*)(row + 1024 + kg) = HH;
}

// ---------------------------------------------------------------------------
// Weight transpose + extend: W fp32 [512][N] -> Bt bf16 [N][1536] = [hi|hi|lo]
// ---------------------------------------------------------------------------
__global__ __launch_bounds__(256) void conv_bt_ext(
    const float* __restrict__ W, __nv_bfloat16* __restrict__ bt, int N)
{
    __shared__ float t[32][33];
    const int n0 = blockIdx.x * 32, k0 = blockIdx.y * 32;
    const int tx = threadIdx.x, ty = threadIdx.y;
#pragma unroll
    for (int r = 0; r < 32; r += 8)
        t[ty + r][tx] = W[(size_t)(k0 + ty + r) * N + n0 + tx];
    __syncthreads();
#pragma unroll
    for (int r = 0; r < 32; r += 8) {
        float x = t[tx][ty + r];
        __nv_bfloat16 h = __float2bfloat16_rn(x);
        __nv_bfloat16 l = __float2bfloat16_rn(x - __bfloat162float(h));
        __nv_bfloat16* row = bt + (size_t)(n0 + ty + r) * KE;
        row[k0 + tx]        = h;
        row[512 + k0 + tx]  = h;
        row[1024 + k0 + tx] = l;
    }
}

// ---------------------------------------------------------------------------
// bf16 WMMA GEMM: C[M,N] fp32 = Aext[M,KE] @ Bt[N,KE]^T
// CTA tile 128x128, 4 warps, warp tile 64x64. K-chunk 64, double-buffered.
// SPLIT=0: fp32 C. SPLIT=1: write bf16 hi/lo pair (staged through smem).
// ---------------------------------------------------------------------------
#define LD2 72
#define HG_SMEM (4 * 128 * LD2 * 2)   // 73728 bytes

template<int SPLIT>
__global__ __launch_bounds__(128) void hgemm(
    const __nv_bfloat16* __restrict__ A,
    const __nv_bfloat16* __restrict__ Bt,
    float* __restrict__ C,
    __nv_bfloat16* __restrict__ Ch, __nv_bfloat16* __restrict__ Cl,
    int M, int N)
{
    extern __shared__ __align__(16) __nv_bfloat16 sm2[];
    __nv_bfloat16* Asm[2] = { sm2,                 sm2 + 128 * LD2 };
    __nv_bfloat16* Bsm[2] = { sm2 + 2 * 128 * LD2, sm2 + 3 * 128 * LD2 };
    uint32_t asa[2], bsa[2];
#pragma unroll
    for (int s = 0; s < 2; s++) {
        asa[s] = (uint32_t)__cvta_generic_to_shared(Asm[s]);
        bsa[s] = (uint32_t)__cvta_generic_to_shared(Bsm[s]);
    }

    const int tid = threadIdx.x;
    const int wid = tid >> 5;
    const int lane = tid & 31;
    const int m0 = blockIdx.y * 128, n0 = blockIdx.x * 128;
    const int wm = (wid >> 1) * 64;
    const int wn = (wid & 1) * 64;

    wmma::fragment<wmma::accumulator, 16, 16, 16, float> cf[4][4];
#pragma unroll
    for (int i = 0; i < 4; i++)
#pragma unroll
        for (int j = 0; j < 4; j++) wmma::fill_fragment(cf[i][j], 0.f);

    auto load_stage = [&](int s, int kc) {
#pragma unroll
        for (int u = 0; u < 8; u++) {
            int chunk = tid + u * 128;
            int row = chunk >> 3;
            int c = (chunk & 7) * 8;
            cp16(asa[s] + (uint32_t)(row * LD2 + c) * 2,
                 A + (size_t)(m0 + row) * KE + kc + c);
        }
#pragma unroll
        for (int u = 0; u < 8; u++) {
            int chunk = tid + u * 128;
            int row = chunk >> 3;
            int c = (chunk & 7) * 8;
            cp16(bsa[s] + (uint32_t)(row * LD2 + c) * 2,
                 Bt + (size_t)(n0 + row) * KE + kc + c);
        }
    };

    load_stage(0, 0);
    cp_commit();

    const int NKC = KE / 64;   // 24
    for (int kc = 0; kc < NKC; kc++) {
        int cur = kc & 1;
        if (kc + 1 < NKC) {
            load_stage(cur ^ 1, (kc + 1) * 64);
            cp_commit();
            cp_wait<1>();
        } else {
            cp_wait<0>();
        }
        __syncthreads();

#pragma unroll
        for (int kk = 0; kk < 64; kk += 16) {
            wmma::fragment<wmma::matrix_a, 16, 16, 16, __nv_bfloat16, wmma::row_major> af[4];
            wmma::fragment<wmma::matrix_b, 16, 16, 16, __nv_bfloat16, wmma::col_major> bf[4];
#pragma unroll
            for (int i = 0; i < 4; i++)
                wmma::load_matrix_sync(af[i], Asm[cur] + (wm + i * 16) * LD2 + kk, LD2);
#pragma unroll
            for (int j = 0; j < 4; j++)
                wmma::load_matrix_sync(bf[j], Bsm[cur] + (wn + j * 16) * LD2 + kk, LD2);
#pragma unroll
            for (int i = 0; i < 4; i++)
#pragma unroll
                for (int j = 0; j < 4; j++)
                    wmma::mma_sync(cf[i][j], af[i], bf[j], cf[i][j]);
        }
        __syncthreads();
    }

    if (SPLIT == 0) {
#pragma unroll
        for (int i = 0; i < 4; i++)
#pragma unroll
            for (int j = 0; j < 4; j++)
                wmma::store_matrix_sync(C + (size_t)(m0 + wm + i * 16) * N + n0 + wn + j * 16,
                                        cf[i][j], N, wmma::mem_row_major);
    } else {
        // stage fp32 per-warp (disjoint regions), then split to bf16 hi/lo
        float* stage = (float*)sm2 + wid * (64 * 68);
#pragma unroll
        for (int i = 0; i < 4; i++)
#pragma unroll
            for (int j = 0; j < 4; j++)
                wmma::store_matrix_sync(stage + i * 16 * 68 + j * 16, cf[i][j], 68,
                                        wmma::mem_row_major);
        __syncwarp();
#pragma unroll 4
        for (int it = lane; it < 64 * 16; it += 32) {
            int rr = it >> 4, cc = (it & 15) * 4;
            float4 v = *(float4*)(stage + rr * 68 + cc);
            size_t go = (size_t)(m0 + wm + rr) * N + n0 + wn + cc;
            split_store(Ch, Cl, go, v);
        }
    }
}

// ---------------------------------------------------------------------------
// WMMA flash attention. K/V/rk arrive as precomputed bf16 hi/lo (cp.async).
// G computes only the 5 needed fragment-column blocks per row block.
// ---------------------------------------------------------------------------
#define LDB 72    // bf16 tile stride (elems)
#define LDF 68    // fp32 AC/PVt stride
#define LDG 132   // fp32 G stride
#define ATTN_SMEM_BYTES 197632

__global__ __launch_bounds__(256) void attn_kernel(
    const float* __restrict__ qb,
    const __nv_bfloat16* __restrict__ kvh, const __nv_bfloat16* __restrict__ kvl,
    const __nv_bfloat16* __restrict__ rkh, const __nv_bfloat16* __restrict__ rkl,
    const float* __restrict__ rwb, const float* __restrict__ rrb,
    float* __restrict__ vec)
{
    extern __shared__ __align__(16) char smem[];
    __nv_bfloat16* bs = (__nv_bfloat16*)smem;
    __nv_bfloat16* qwh = bs;
    __nv_bfloat16* qwl = bs + 1 * 64 * LDB;
    __nv_bfloat16* qrh = bs + 2 * 64 * LDB;
    __nv_bfloat16* qrl = bs + 3 * 64 * LDB;
    __nv_bfloat16* kh  = bs + 4 * 64 * LDB;
    __nv_bfloat16* kl  = bs + 5 * 64 * LDB;
    __nv_bfloat16* vh  = bs + 6 * 64 * LDB;
    __nv_bfloat16* vl  = bs + 7 * 64 * LDB;
    __nv_bfloat16* ph  = bs + 8 * 64 * LDB;
    __nv_bfloat16* pl  = bs + 9 * 64 * LDB;
    __nv_bfloat16* rh[2] = { bs + 10 * 64 * LDB, bs + 12 * 64 * LDB };
    __nv_bfloat16* rl[2] = { bs + 11 * 64 * LDB, bs + 13 * 64 * LDB };
    float* AC  = (float*)(smem + 14 * 64 * LDB * 2);
    float* G   = AC + 64 * LDF;
    float* PVt = G + 64 * LDG;

    const uint32_t kh_a = (uint32_t)__cvta_generic_to_shared(kh);
    const uint32_t kl_a = (uint32_t)__cvta_generic_to_shared(kl);
    const uint32_t vh_a = (uint32_t)__cvta_generic_to_shared(vh);
    const uint32_t vl_a = (uint32_t)__cvta_generic_to_shared(vl);
    const uint32_t rh_a[2] = { (uint32_t)__cvta_generic_to_shared(rh[0]),
                               (uint32_t)__cvta_generic_to_shared(rh[1]) };
    const uint32_t rl_a[2] = { (uint32_t)__cvta_generic_to_shared(rl[0]),
                               (uint32_t)__cvta_generic_to_shared(rl[1]) };

    const int tid = threadIdx.x;
    const int wid = tid >> 5;
    const int tx = tid & 15;
    const int ty = tid >> 4;
    const int bn = blockIdx.y;
    const int b = bn >> 3;
    const int n = bn & 7;
    const int ib = 15 - blockIdx.x;      // longest CTAs first
    const int i0 = ib * 64;
    const int iw = ty * 4;
    const int jc = tx * 4;
    const int h0 = 15 - ib;              // first rk half index
    const int ntiles = ib + 17;

    const int fi = wid >> 1;             // warp frag row (0..3)
    const int half = wid & 1;

    // ---- prologue: rk lower half via cp.async; Q tiles (+biases, hi/lo) ----
#pragma unroll
    for (int u = 0; u < 2; u++) {
        int ch = tid + u * 256;
        int row = ch >> 3, c = (ch & 7) * 8;
        int d = h0 * 64 + row;
        size_t gb = (size_t)d * DM + n * DH + c;
        uint32_t so = (uint32_t)(row * LDB + c) * 2;
        cp16(rh_a[h0 & 1] + so, rkh + gb);
        cp16(rl_a[h0 & 1] + so, rkl + gb);
    }
    cp_commit();
#pragma unroll
    for (int u = 0; u < 4; u++) {
        int it = tid + u * 256;
        int row = it >> 4, cg = (it & 15) * 4;
        float4 qv = *(const float4*)(qb + (size_t)((i0 + row) * BSZ + b) * DM + n * DH + cg);
        float4 wv = *(const float4*)(rwb + n * DH + cg);
        float4 rv = *(const float4*)(rrb + n * DH + cg);
        split_store(qwh, qwl, row * LDB + cg,
                    make_float4(qv.x + wv.x, qv.y + wv.y, qv.z + wv.z, qv.w + wv.w));
        split_store(qrh, qrl, row * LDB + cg,
                    make_float4(qv.x + rv.x, qv.y + rv.y, qv.z + rv.z, qv.w + rv.w));
    }
    cp_wait<0>();
    __syncthreads();

    float m[4], l[4], o[4][4];
#pragma unroll
    for (int i = 0; i < 4; i++) {
        m[i] = -1e30f; l[i] = 0.f;
#pragma unroll
        for (int j = 0; j < 4; j++) o[i][j] = 0.f;
    }

    for (int t = 0; t < ntiles; t++) {
        const int j0 = t * 64;
        const int hb = h0 + t;
        const int hu = hb + 1;

        // ---- async loads: K, V (hi/lo) and new rk half ----
#pragma unroll
        for (int u = 0; u < 2; u++) {
            int ch = tid + u * 256;
            int row = ch >> 3, c = (ch & 7) * 8;
            size_t gb = (size_t)((j0 + row) * BSZ + b) * (2 * DM) + n * DH + c;
            uint32_t so = (uint32_t)(row * LDB + c) * 2;
            cp16(kh_a + so, kvh + gb);
            cp16(kl_a + so, kvl + gb);
            cp16(vh_a + so, kvh + gb + DM);
            cp16(vl_a + so, kvl + gb + DM);
        }
#pragma unroll
        for (int u = 0; u < 2; u++) {
            int ch = tid + u * 256;
            int row = ch >> 3, c = (ch & 7) * 8;
            int d = hu * 64 + row;
            int ok = (d < KLEN) ? 16 : 0;
            size_t gb = (size_t)(d < KLEN ? d : 0) * DM + n * DH + c;
            uint32_t so = (uint32_t)(row * LDB + c) * 2;
            cp16z(rh_a[hu & 1] + so, rkh + gb, ok);
            cp16z(rl_a[hu & 1] + so, rkl + gb, ok);
        }
        cp_commit();
        cp_wait<0>();
        __syncthreads();

        // ---- WMMA: AC (64x64) ----
        {
            wmma::fragment<wmma::accumulator, 16, 16, 16, float> acc[2];
            wmma::fill_fragment(acc[0], 0.f);
            wmma::fill_fragment(acc[1], 0.f);
#pragma unroll
            for (int k = 0; k < 4; k++) {
                int k16 = k * 16;
                wmma::fragment<wmma::matrix_a, 16, 16, 16, __nv_bfloat16, wmma::row_major> ah, al;
                wmma::load_matrix_sync(ah, qwh + fi * 16 * LDB + k16, LDB);
                wmma::load_matrix_sync(al, qwl + fi * 16 * LDB + k16, LDB);
#pragma unroll
                for (int q = 0; q < 2; q++) {
                    int fj = half * 2 + q;
                    wmma::fragment<wmma::matrix_b, 16, 16, 16, __nv_bfloat16, wmma::col_major> bh, bl;
                    wmma::load_matrix_sync(bh, kh + fj * 16 * LDB + k16, LDB);
                    wmma::load_matrix_sync(bl, kl + fj * 16 * LDB + k16, LDB);
                    wmma::mma_sync(acc[q], ah, bh, acc[q]);
                    wmma::mma_sync(acc[q], al, bh, acc[q]);
                    wmma::mma_sync(acc[q], ah, bl, acc[q]);
                }
            }
#pragma unroll
            for (int q = 0; q < 2; q++) {
                int fj = half * 2 + q;
                wmma::store_matrix_sync(AC + fi * 16 * LDF + fj * 16, acc[q], LDF,
                                        wmma::mem_row_major);
            }
        }
        // ---- WMMA: G band (5 of 8 fragment cols per row block) ----
        {
            const int nfr = half ? 2 : 3;
            const int fb0 = 3 - fi + (half ? 3 : 0);
            wmma::fragment<wmma::accumulator, 16, 16, 16, float> acc[3];
#pragma unroll
            for (int q = 0; q < 3; q++) wmma::fill_fragment(acc[q], 0.f);
#pragma unroll
            for (int k = 0; k < 4; k++) {
                int k16 = k * 16;
                wmma::fragment<wmma::matrix_a, 16, 16, 16, __nv_bfloat16, wmma::row_major> ah, al;
                wmma::load_matrix_sync(ah, qrh + fi * 16 * LDB + k16, LDB);
                wmma::load_matrix_sync(al, qrl + fi * 16 * LDB + k16, LDB);
#pragma unroll
                for (int q = 0; q < 3; q++) {
                    if (q < nfr) {
                        int fjg = fb0 + q;
                        int slot = (hb + (fjg >> 2)) & 1;
                        int rbase = (fjg & 3) * 16 * LDB;
                        wmma::fragment<wmma::matrix_b, 16, 16, 16, __nv_bfloat16, wmma::col_major> bh, bl;
                        wmma::load_matrix_sync(bh, rh[slot] + rbase + k16, LDB);
                        wmma::load_matrix_sync(bl, rl[slot] + rbase + k16, LDB);
                        wmma::mma_sync(acc[q], ah, bh, acc[q]);
                        wmma::mma_sync(acc[q], al, bh, acc[q]);
                        wmma::mma_sync(acc[q], ah, bl, acc[q]);
                    }
                }
            }
#pragma unroll
            for (int q = 0; q < 3; q++)
                if (q < nfr)
                    wmma::store_matrix_sync(G + fi * 16 * LDG + (fb0 + q) * 16, acc[q], LDG,
                                            wmma::mem_row_major);
        }
        __syncthreads();

        // ---- softmax (fp32) + P hi/lo write + O rescale ----
#pragma unroll
        for (int ii = 0; ii < 4; ii++) {
            const int ig = i0 + iw + ii;
            float s[4];
            float mx = -1e30f;
#pragma unroll
            for (int jj = 0; jj < 4; jj++) {
                int jg = j0 + jc + jj;
                float v = (AC[(iw + ii) * LDF + jc + jj]
                         + G[(iw + ii) * LDG + (jc + jj) - (iw + ii) + 63]) * SCALE;
                if (jg > ig + MLEN) v = -1e30f;
                s[jj] = v;
                mx = fmaxf(mx, v);
            }
#pragma unroll
            for (int off = 8; off >= 1; off >>= 1)
                mx = fmaxf(mx, __shfl_xor_sync(0xffffffffu, mx, off));
            float mnew = fmaxf(m[ii], mx);
            float f = __expf(m[ii] - mnew);
            float rs = 0.f;
#pragma unroll
            for (int jj = 0; jj < 4; jj++) {
                float p = __expf(s[jj] - mnew);
                __nv_bfloat16 hp = __float2bfloat16_rn(p);
                ph[(iw + ii) * LDB + jc + jj] = hp;
                pl[(iw + ii) * LDB + jc + jj] = __float2bfloat16_rn(p - __bfloat162float(hp));
                rs += p;
            }
#pragma unroll
            for (int off = 8; off >= 1; off >>= 1)
                rs += __shfl_xor_sync(0xffffffffu, rs, off);
            l[ii] = l[ii] * f + rs;
            m[ii] = mnew;
#pragma unroll
            for (int kk = 0; kk < 4; kk++) o[ii][kk] *= f;
        }
        __syncthreads();

        // ---- WMMA PV (3-term) into PVt ----
        {
            wmma::fragment<wmma::accumulator, 16, 16, 16, float> acc[2];
            wmma::fill_fragment(acc[0], 0.f);
            wmma::fill_fragment(acc[1], 0.f);
#pragma unroll
            for (int k = 0; k < 4; k++) {
                int k16 = k * 16;
                wmma::fragment<wmma::matrix_a, 16, 16, 16, __nv_bfloat16, wmma::row_major> ah, al;
                wmma::load_matrix_sync(ah, ph + fi * 16 * LDB + k16, LDB);
                wmma::load_matrix_sync(al, pl + fi * 16 * LDB + k16, LDB);
#pragma unroll
                for (int q = 0; q < 2; q++) {
                    int fj = half * 2 + q;
                    wmma::fragment<wmma::matrix_b, 16, 16, 16, __nv_bfloat16, wmma::row_major> bh, bl;
                    wmma::load_matrix_sync(bh, vh + k16 * LDB + fj * 16, LDB);
                    wmma::load_matrix_sync(bl, vl + k16 * LDB + fj * 16, LDB);
                    wmma::mma_sync(acc[q], ah, bh, acc[q]);
                    wmma::mma_sync(acc[q], al, bh, acc[q]);
                    wmma::mma_sync(acc[q], ah, bl, acc[q]);
                }
            }
#pragma unroll
            for (int q = 0; q < 2; q++) {
                int fj = half * 2 + q;
                wmma::store_matrix_sync(PVt + fi * 16 * LDF + fj * 16, acc[q], LDF,
                                        wmma::mem_row_major);
            }
        }
        __syncthreads();

        // ---- O += PVt ----
#pragma unroll
        for (int ii = 0; ii < 4; ii++)
#pragma unroll
            for (int kk = 0; kk < 4; kk++)
                o[ii][kk] += PVt[(iw + ii) * LDF + jc + kk];
    }

    // ---- epilogue ----
#pragma unroll
    for (int ii = 0; ii < 4; ii++) {
        float inv = 1.f / l[ii];
        float4 v = make_float4(o[ii][0] * inv, o[ii][1] * inv,
                               o[ii][2] * inv, o[ii][3] * inv);
        *(float4*)(vec + (size_t)((i0 + iw + ii) * BSZ + b) * DM + n * DH + jc) = v;
    }
}

// ---------------------------------------------------------------------------
// Residual + LayerNorm (unchanged)
// ---------------------------------------------------------------------------
__global__ __launch_bounds__(256) void ln_kernel(
    const float* __restrict__ w, const float* __restrict__ ao,
    const float* __restrict__ g, const float* __restrict__ bb,
    float* __restrict__ out)
{
    const int row = blockIdx.x;
    const int tid = threadIdx.x;
    const size_t base = (size_t)row * DM;

    float x0 = w[base + tid]       + ao[base + tid];
    float x1 = w[base + tid + 256] + ao[base + tid + 256];
    float s  = x0 + x1;
    float ss = x0 * x0 + x1 * x1;

#pragma unroll
    for (int off = 16; off >= 1; off >>= 1) {
        s  += __shfl_xor_sync(0xffffffffu, s,  off);
        ss += __shfl_xor_sync(0xffffffffu, ss, off);
    }
    __shared__ float sh_s[8], sh_ss[8];
    int wid = tid >> 5, lane = tid & 31;
    if (lane == 0) { sh_s[wid] = s; sh_ss[wid] = ss; }
    __syncthreads();
    if (tid == 0) {
        float a = 0.f, c = 0.f;
#pragma unroll
        for (int i = 0; i < 8; i++) { a += sh_s[i]; c += sh_ss[i]; }
        sh_s[0] = a; sh_ss[0] = c;
    }
    __syncthreads();

    float mean = sh_s[0] * (1.f / (float)DM);
    float var  = sh_ss[0] * (1.f / (float)DM) - mean * mean;
    float rstd = rsqrtf(var + LN_EPS);

    out[base + tid]       = (x0 - mean) * rstd * g[tid]       + bb[tid];
    out[base + tid + 256] = (x1 - mean) * rstd * g[tid + 256] + bb[tid + 256];
}

// ---------------------------------------------------------------------------
// Launcher
// ---------------------------------------------------------------------------
extern "C" void kernel_launch(void* const* d_in, const int* in_sizes, int n_in,
                              void* d_out, int out_size)
{
    const float* w    = (const float*)d_in[0];
    const float* r    = (const float*)d_in[1];
    const float* rwb  = (const float*)d_in[2];
    const float* rrb  = (const float*)d_in[3];
    const float* mems = (const float*)d_in[4];
    const float* Wq   = (const float*)d_in[5];
    const float* Wkv  = (const float*)d_in[6];
    const float* Wr   = (const float*)d_in[7];
    const float* Wo   = (const float*)d_in[8];
    const float* lng  = (const float*)d_in[9];
    const float* lnb  = (const float*)d_in[10];
    float* out = (float*)d_out;

    float *q, *vec, *ao;
    cudaGetSymbolAddress((void**)&q,   g_q);
    cudaGetSymbolAddress((void**)&vec, g_vec);
    cudaGetSymbolAddress((void**)&ao,  g_ao);
    __nv_bfloat16 *kvh, *kvl, *rkh, *rkl;
    cudaGetSymbolAddress((void**)&kvh, g_kvh);
    cudaGetSymbolAddress((void**)&kvl, g_kvl);
    cudaGetSymbolAddress((void**)&rkh, g_rkh);
    cudaGetSymbolAddress((void**)&rkl, g_rkl);
    __nv_bfloat16 *axm, *axw, *axr, *axv, *btkv, *btq, *btr, *bto;
    cudaGetSymbolAddress((void**)&axm,  g_ax_mem);
    cudaGetSymbolAddress((void**)&axw,  g_ax_w);
    cudaGetSymbolAddress((void**)&axr,  g_ax_r);
    cudaGetSymbolAddress((void**)&axv,  g_ax_v);
    cudaGetSymbolAddress((void**)&btkv, g_bt_kv);
    cudaGetSymbolAddress((void**)&btq,  g_bt_q);
    cudaGetSymbolAddress((void**)&btr,  g_bt_r);
    cudaGetSymbolAddress((void**)&bto,  g_bt_o);

    cudaFuncSetAttribute(attn_kernel, cudaFuncAttributeMaxDynamicSharedMemorySize,
                         ATTN_SMEM_BYTES);
    cudaFuncSetAttribute(hgemm<0>, cudaFuncAttributeMaxDynamicSharedMemorySize, HG_SMEM);
    cudaFuncSetAttribute(hgemm<1>, cudaFuncAttributeMaxDynamicSharedMemorySize, HG_SMEM);

    // Operand conversions (hi/lo K-extension)
    conv_a_ext<<<2048, 256>>>(mems, axm);
    conv_a_ext<<<2048, 256>>>(w, axw);
    conv_a_ext<<<1024, 256>>>(r, axr);
    conv_bt_ext<<<dim3(32, 16), dim3(32, 8)>>>(Wkv, btkv, 1024);
    conv_bt_ext<<<dim3(16, 16), dim3(32, 8)>>>(Wq,  btq,  512);
    conv_bt_ext<<<dim3(16, 16), dim3(32, 8)>>>(Wr,  btr,  512);
    conv_bt_ext<<<dim3(16, 16), dim3(32, 8)>>>(Wo,  bto,  512);

    // Projection GEMMs (HMMA). kv and rk write bf16 hi/lo directly.
    hgemm<1><<<dim3(8, 32), 128, HG_SMEM>>>(axm, btkv, nullptr, kvh, kvl, 4096, 1024);
    hgemm<1><<<dim3(8, 32), 128, HG_SMEM>>>(axw, btkv, nullptr,
                                            kvh + (size_t)4096 * 1024,
                                            kvl + (size_t)4096 * 1024, 4096, 1024);
    hgemm<0><<<dim3(4, 32), 128, HG_SMEM>>>(axw, btq, q, nullptr, nullptr, 4096, 512);
    hgemm<1><<<dim3(4, 16), 128, HG_SMEM>>>(axr, btr, nullptr, rkh, rkl, 2048, 512);

    // WMMA flash attention
    attn_kernel<<<dim3(16, 32), 256, ATTN_SMEM_BYTES>>>(q, kvh, kvl, rkh, rkl,
                                                        rwb, rrb, vec);

    // attn_out = vec @ Wo (HMMA)
    conv_a_ext<<<2048, 256>>>(vec, axv);
    hgemm<0><<<dim3(4, 32), 128, HG_SMEM>>>(axv, bto, ao, nullptr, nullptr, 4096, 512);

    // residual + layernorm -> d_out
    ln_kernel<<<QLEN * BSZ, 256>>>(w, ao, lng, lnb, out);
}